// round 11
// baseline (speedup 1.0000x reference)
#include <cuda_runtime.h>
#include <cuda_fp16.h>
#include <math.h>
#include <stdint.h>

// ============================================================================
// MLA prefill — round 11: R10 + accumulator-RAW-chain fix.
// The 3 split-precision passes (hh, hl, lh) were issued back-to-back per
// accumulator (asm volatile = no reordering) -> 3-deep RAW chains on ~20cyc
// HMMA latency -> tensor pipe 46.6% busy. Now pass-outer ordering: 16
// independent mmas between any accumulator reuse. Same per-acc addition
// order -> bit-identical results (rel_err 2.1e-5).
// ============================================================================

#define SB     2
#define SEQL   2048
#define DMODEL 2048
#define CLAT   512
#define NH     16
#define DHD    128
#define HDTOT  2048

// ---------------- scratch ----------------
__device__ __half g_xh [(size_t)SB * SEQL * DMODEL],  g_xl [(size_t)SB * SEQL * DMODEL];
__device__ __half g_wdh[(size_t)CLAT * DMODEL],       g_wdl[(size_t)CLAT * DMODEL];
__device__ __half g_wqh[(size_t)HDTOT * DMODEL],      g_wql[(size_t)HDTOT * DMODEL];
__device__ __half g_wuvh[(size_t)HDTOT * CLAT],       g_wuvl[(size_t)HDTOT * CLAT];
__device__ __half g_woh[(size_t)DMODEL * HDTOT],      g_wol[(size_t)DMODEL * HDTOT];
__device__ __half g_wukTh[(size_t)NH * CLAT * DHD],   g_wukTl[(size_t)NH * CLAT * DHD];
__device__ float  g_lat  [(size_t)SB * SEQL * CLAT];
__device__ __half g_lath [(size_t)SB * SEQL * CLAT],  g_latl [(size_t)SB * SEQL * CLAT];
__device__ __half g_latTh[(size_t)SB * CLAT * SEQL],  g_latTl[(size_t)SB * CLAT * SEQL];
__device__ __half g_qh   [(size_t)SB * SEQL * HDTOT], g_ql   [(size_t)SB * SEQL * HDTOT];
__device__ __half g_qlath[(size_t)SB * NH * SEQL * CLAT], g_qlatl[(size_t)SB * NH * SEQL * CLAT];
__device__ float  g_scores[(size_t)SB * NH * SEQL * SEQL];
__device__ __half g_attnh[(size_t)SB * NH * SEQL * SEQL], g_attnl[(size_t)SB * NH * SEQL * SEQL];
__device__ __half g_ctxh [(size_t)SB * NH * SEQL * CLAT], g_ctxl [(size_t)SB * NH * SEQL * CLAT];
__device__ __half g_vh   [(size_t)SB * SEQL * HDTOT], g_vl   [(size_t)SB * SEQL * HDTOT];

#define BM 128
#define BN 128
#define BK 32
#define ROWH 40      // smem row pitch in halves (32 data + 8 pad): conflict-free
#define TILEH (BM * ROWH)
#define SMEM_BYTES (2 * 4 * TILEH * 2)          // 81920 B

// m16n8k16 fp16 mma, fp32 accumulate. NOT volatile: scheduler may interleave.
static __device__ __forceinline__ void mma_16816(float* d, const uint32_t* a,
                                                 const uint32_t* b) {
    asm("mma.sync.aligned.m16n8k16.row.col.f32.f16.f16.f32 "
        "{%0,%1,%2,%3}, {%4,%5,%6,%7}, {%8,%9}, {%0,%1,%2,%3};"
        : "+f"(d[0]), "+f"(d[1]), "+f"(d[2]), "+f"(d[3])
        : "r"(a[0]), "r"(a[1]), "r"(a[2]), "r"(a[3]), "r"(b[0]), "r"(b[1]));
}

static __device__ __forceinline__ void fsplit(float f, __half& h, __half& l) {
    h = __float2half_rn(f);
    l = __float2half_rn(f - __half2float(h));
}

// cp.async one 128x32-half tile (8KB): 512 16B chunks, 2 per thread.
static __device__ __forceinline__ void pf_tile(__half* s, const __half* g, int ld, int tid) {
#pragma unroll
    for (int i = 0; i < 2; i++) {
        const int idx = tid + i * 256;
        const int r = idx >> 2;
        const int c = (idx & 3) << 3;
        unsigned dst = (unsigned)__cvta_generic_to_shared(s + r * ROWH + c);
        asm volatile("cp.async.cg.shared.global [%0], [%1], 16;"
                     :: "r"(dst), "l"(g + (long long)r * ld + c));
    }
}

// ---------------------------------------------------------------------------
// GEMM: C[128m,128n] = alpha * A @ B^T, A[M,K] hi/lo halves, B[N,K] hi/lo.
// MODE 0: plain. 1: G3. 2: G4 (causal skip). 3: G6 (K_eff). 4: G7.
// OUTK 0: fp32 C. 1: hi/lo half C. 2: both.
// 256 threads = 8 warps (2m x 4n); warp tile 64x32 = 4x4 m16n8k16 atoms.
// ---------------------------------------------------------------------------
template<int MODE, int OUTK>
__global__ void __launch_bounds__(256)
mma_gemm(const __half* __restrict__ Ah, const __half* __restrict__ Al,
         const __half* __restrict__ Bh, const __half* __restrict__ Bl,
         float* __restrict__ C, __half* __restrict__ Ch, __half* __restrict__ Cl,
         int K, int lda, int ldb, int ldc, float alpha)
{
    const int bn = blockIdx.x;
    const int bm = blockIdx.y;
    const int z  = blockIdx.z;

    if (MODE == 2 && bn > bm) return;

    long long aoff = 0, boff = 0, coff = 0;
    if (MODE == 1) {
        int b = z >> 4, h = z & 15;
        aoff = (long long)b * SEQL * HDTOT + (long long)h * DHD;
        boff = (long long)h * CLAT * DHD;
        coff = (long long)z * SEQL * CLAT;
    } else if (MODE == 2) {
        aoff = (long long)z * SEQL * CLAT;
        boff = (long long)(z >> 4) * SEQL * CLAT;
        coff = (long long)z * SEQL * SEQL;
    } else if (MODE == 3) {
        aoff = (long long)z * SEQL * SEQL;
        boff = (long long)(z >> 4) * CLAT * SEQL;
        coff = (long long)z * SEQL * CLAT;
    } else if (MODE == 4) {
        int b = z >> 4, h = z & 15;
        aoff = (long long)z * SEQL * CLAT;
        boff = (long long)h * DHD * CLAT;
        coff = (long long)b * SEQL * HDTOT + (long long)h * DHD;
    }

    const int Keff = (MODE == 3) ? min(K, (bm + 1) * BM) : K;
    const int nkt = Keff / BK;

    const __half* Abh = Ah + aoff + (long long)bm * BM * lda;
    const __half* Abl = Al + aoff + (long long)bm * BM * lda;
    const __half* Bbh = Bh + boff + (long long)bn * BN * ldb;
    const __half* Bbl = Bl + boff + (long long)bn * BN * ldb;
    const long long cbase = coff + (long long)bm * BM * ldc + (long long)bn * BN;

    extern __shared__ __half dynsm[];
#define SMT(buf, op) (dynsm + ((buf) * 4 + (op)) * TILEH)

    const int tid  = threadIdx.x;
    const int lane = tid & 31;
    const int w    = tid >> 5;
    const int mo = (w >> 2) * 64;
    const int no = (w & 3) * 32;
    const int g  = lane >> 2;
    const int t  = lane & 3;

    float acc[4][4][4];
#pragma unroll
    for (int mt = 0; mt < 4; mt++)
#pragma unroll
        for (int nt = 0; nt < 4; nt++)
#pragma unroll
            for (int e = 0; e < 4; e++) acc[mt][nt][e] = 0.f;

    pf_tile(SMT(0, 0), Abh, lda, tid);
    pf_tile(SMT(0, 1), Abl, lda, tid);
    pf_tile(SMT(0, 2), Bbh, ldb, tid);
    pf_tile(SMT(0, 3), Bbl, ldb, tid);
    asm volatile("cp.async.commit_group;");

    for (int kt = 0; kt < nkt; ++kt) {
        const int buf = kt & 1;
        if (kt + 1 < nkt) {
            const long long ko = (long long)(kt + 1) * BK;
            pf_tile(SMT(buf ^ 1, 0), Abh + ko, lda, tid);
            pf_tile(SMT(buf ^ 1, 1), Abl + ko, lda, tid);
            pf_tile(SMT(buf ^ 1, 2), Bbh + ko, ldb, tid);
            pf_tile(SMT(buf ^ 1, 3), Bbl + ko, ldb, tid);
            asm volatile("cp.async.commit_group;");
            asm volatile("cp.async.wait_group 1;");
        } else {
            asm volatile("cp.async.wait_group 0;");
        }
        __syncthreads();

        const __half* Ahb = SMT(buf, 0);
        const __half* Alb = SMT(buf, 1);
        const __half* Bhb = SMT(buf, 2);
        const __half* Blb = SMT(buf, 3);

#pragma unroll
        for (int ks = 0; ks < 2; ks++) {        // two k16 steps per BK=32 tile
            const int kk = ks * 16;
            uint32_t ah[4][4], al[4][4], bh[4][2], bl[4][2];
#pragma unroll
            for (int mt = 0; mt < 4; mt++) {
                const int base = (mo + mt * 16 + g) * ROWH + kk + 2 * t;
                ah[mt][0] = *reinterpret_cast<const uint32_t*>(Ahb + base);
                ah[mt][1] = *reinterpret_cast<const uint32_t*>(Ahb + base + 8 * ROWH);
                ah[mt][2] = *reinterpret_cast<const uint32_t*>(Ahb + base + 8);
                ah[mt][3] = *reinterpret_cast<const uint32_t*>(Ahb + base + 8 * ROWH + 8);
                al[mt][0] = *reinterpret_cast<const uint32_t*>(Alb + base);
                al[mt][1] = *reinterpret_cast<const uint32_t*>(Alb + base + 8 * ROWH);
                al[mt][2] = *reinterpret_cast<const uint32_t*>(Alb + base + 8);
                al[mt][3] = *reinterpret_cast<const uint32_t*>(Alb + base + 8 * ROWH + 8);
            }
#pragma unroll
            for (int nt = 0; nt < 4; nt++) {
                const int base = (no + nt * 8 + g) * ROWH + kk + 2 * t;
                bh[nt][0] = *reinterpret_cast<const uint32_t*>(Bhb + base);
                bh[nt][1] = *reinterpret_cast<const uint32_t*>(Bhb + base + 8);
                bl[nt][0] = *reinterpret_cast<const uint32_t*>(Blb + base);
                bl[nt][1] = *reinterpret_cast<const uint32_t*>(Blb + base + 8);
            }

            // pass-outer ordering: 16 independent mmas per pass, accumulator
            // reuse only after a full pass (RAW chains hidden). Per-acc
            // addition order unchanged: hh, then hl, then lh.
#pragma unroll
            for (int mt = 0; mt < 4; mt++)
#pragma unroll
                for (int nt = 0; nt < 4; nt++)
                    mma_16816(acc[mt][nt], ah[mt], bh[nt]);
#pragma unroll
            for (int mt = 0; mt < 4; mt++)
#pragma unroll
                for (int nt = 0; nt < 4; nt++)
                    mma_16816(acc[mt][nt], ah[mt], bl[nt]);
#pragma unroll
            for (int mt = 0; mt < 4; mt++)
#pragma unroll
                for (int nt = 0; nt < 4; nt++)
                    mma_16816(acc[mt][nt], al[mt], bh[nt]);
        }
        __syncthreads();
    }
#undef SMT

#pragma unroll
    for (int mt = 0; mt < 4; mt++) {
        const int r0 = mo + mt * 16 + g;
#pragma unroll
        for (int nt = 0; nt < 4; nt++) {
            const int ccol = no + nt * 8 + 2 * t;
            const long long i0 = cbase + (long long)r0 * ldc + ccol;
            const long long i1 = cbase + (long long)(r0 + 8) * ldc + ccol;
            float f0 = acc[mt][nt][0] * alpha, f1 = acc[mt][nt][1] * alpha;
            float f2 = acc[mt][nt][2] * alpha, f3 = acc[mt][nt][3] * alpha;
            if (OUTK == 0 || OUTK == 2) {
                *reinterpret_cast<float2*>(C + i0) = make_float2(f0, f1);
                *reinterpret_cast<float2*>(C + i1) = make_float2(f2, f3);
            }
            if (OUTK == 1 || OUTK == 2) {
                __half h0, l0, h1, l1, h2, l2, h3, l3;
                fsplit(f0, h0, l0); fsplit(f1, h1, l1);
                fsplit(f2, h2, l2); fsplit(f3, h3, l3);
                *reinterpret_cast<__half2*>(Ch + i0) = __halves2half2(h0, h1);
                *reinterpret_cast<__half2*>(Cl + i0) = __halves2half2(l0, l1);
                *reinterpret_cast<__half2*>(Ch + i1) = __halves2half2(h2, h3);
                *reinterpret_cast<__half2*>(Cl + i1) = __halves2half2(l2, l3);
            }
        }
    }
}

// ---------------------------------------------------------------------------
__global__ void cvt_kernel(const float* __restrict__ in, __half* __restrict__ oh,
                           __half* __restrict__ ol, long long n)
{
    long long i = (long long)blockIdx.x * blockDim.x + threadIdx.x;
    if (i < n) {
        __half h, l;
        fsplit(in[i], h, l);
        oh[i] = h; ol[i] = l;
    }
}

// ---------------------------------------------------------------------------
__global__ void transpose_cvt_kernel(const float* __restrict__ in,
                                     __half* __restrict__ oh, __half* __restrict__ ol,
                                     int R, int Cc)
{
    __shared__ float tsm[32][33];
    const int z = blockIdx.z;
    const int r0 = blockIdx.y * 32, c0 = blockIdx.x * 32;
    const float* I = in + (long long)z * R * Cc;
    const long long obase = (long long)z * R * Cc;
    const int tx = threadIdx.x, ty = threadIdx.y;
#pragma unroll
    for (int i = 0; i < 32; i += 8)
        tsm[ty + i][tx] = I[(long long)(r0 + ty + i) * Cc + c0 + tx];
    __syncthreads();
#pragma unroll
    for (int i = 0; i < 32; i += 8) {
        __half h, l;
        fsplit(tsm[tx][ty + i], h, l);
        long long o = obase + (long long)(c0 + ty + i) * R + r0 + tx;
        oh[o] = h; ol[o] = l;
    }
}

// ---------------------------------------------------------------------------
// Causal row softmax, single exp per element (store e back, renormalize).
// ---------------------------------------------------------------------------
__global__ void softmax_kernel(float* __restrict__ scores,
                               __half* __restrict__ ph, __half* __restrict__ pl)
{
    const int warp = threadIdx.x >> 5;
    const int lane = threadIdx.x & 31;
    const long long r = (long long)blockIdx.x * (blockDim.x >> 5) + warp;
    const int s = (int)(r & (SEQL - 1));
    const int len = s + 1;
    float* row = scores + r * SEQL;
    __half* rh = ph + r * SEQL;
    __half* rl = pl + r * SEQL;

    float mx = -INFINITY;
    for (int j = lane; j < len; j += 32) mx = fmaxf(mx, row[j]);
#pragma unroll
    for (int o = 16; o > 0; o >>= 1) mx = fmaxf(mx, __shfl_xor_sync(0xffffffffu, mx, o));

    float sum = 0.f;
    for (int j = lane; j < len; j += 32) {
        float e = __expf(row[j] - mx);
        row[j] = e;
        sum += e;
    }
#pragma unroll
    for (int o = 16; o > 0; o >>= 1) sum += __shfl_xor_sync(0xffffffffu, sum, o);

    const float inv = 1.0f / sum;
    for (int j = lane; j < len; j += 32) {
        float p = row[j] * inv;
        __half h, l;
        fsplit(p, h, l);
        rh[j] = h; rl[j] = l;
    }
    const int zend = ((s >> 7) + 1) << 7;
    for (int j = len + lane; j < zend; j += 32) {
        rh[j] = __float2half_rn(0.f); rl[j] = __float2half_rn(0.f);
    }
}

// ---------------------------------------------------------------------------
extern "C" void kernel_launch(void* const* d_in, const int* in_sizes, int n_in,
                              void* d_out, int out_size)
{
    const float* x   = (const float*)d_in[0];
    const float* Wd  = (const float*)d_in[1];
    const float* Wuk = (const float*)d_in[2];
    const float* Wuv = (const float*)d_in[3];
    const float* Wq  = (const float*)d_in[4];
    const float* Wo  = (const float*)d_in[5];
    float* out = (float*)d_out;

#define SYM(p, s) cudaGetSymbolAddress((void**)&p, s)
    __half *xh, *xl, *wdh, *wdl, *wqh, *wql, *wuvh, *wuvl, *woh, *wol, *wukTh, *wukTl;
    __half *lath, *latl, *latTh, *latTl, *qh, *ql, *qlath, *qlatl;
    __half *attnh, *attnl, *ctxh, *ctxl, *vh, *vl;
    float *lat, *sc;
    SYM(xh, g_xh); SYM(xl, g_xl); SYM(wdh, g_wdh); SYM(wdl, g_wdl);
    SYM(wqh, g_wqh); SYM(wql, g_wql); SYM(wuvh, g_wuvh); SYM(wuvl, g_wuvl);
    SYM(woh, g_woh); SYM(wol, g_wol); SYM(wukTh, g_wukTh); SYM(wukTl, g_wukTl);
    SYM(lat, g_lat); SYM(lath, g_lath); SYM(latl, g_latl);
    SYM(latTh, g_latTh); SYM(latTl, g_latTl);
    SYM(qh, g_qh); SYM(ql, g_ql); SYM(qlath, g_qlath); SYM(qlatl, g_qlatl);
    SYM(sc, g_scores); SYM(attnh, g_attnh); SYM(attnl, g_attnl);
    SYM(ctxh, g_ctxh); SYM(ctxl, g_ctxl); SYM(vh, g_vh); SYM(vl, g_vl);
#undef SYM

    static int attr_done = 0;
    if (!attr_done) {
        cudaFuncSetAttribute(mma_gemm<0, 0>, cudaFuncAttributeMaxDynamicSharedMemorySize, SMEM_BYTES);
        cudaFuncSetAttribute(mma_gemm<0, 1>, cudaFuncAttributeMaxDynamicSharedMemorySize, SMEM_BYTES);
        cudaFuncSetAttribute(mma_gemm<0, 2>, cudaFuncAttributeMaxDynamicSharedMemorySize, SMEM_BYTES);
        cudaFuncSetAttribute(mma_gemm<1, 1>, cudaFuncAttributeMaxDynamicSharedMemorySize, SMEM_BYTES);
        cudaFuncSetAttribute(mma_gemm<2, 0>, cudaFuncAttributeMaxDynamicSharedMemorySize, SMEM_BYTES);
        cudaFuncSetAttribute(mma_gemm<3, 1>, cudaFuncAttributeMaxDynamicSharedMemorySize, SMEM_BYTES);
        cudaFuncSetAttribute(mma_gemm<4, 1>, cudaFuncAttributeMaxDynamicSharedMemorySize, SMEM_BYTES);
        attr_done = 1;
    }

    const int MROWS = SB * SEQL;  // 4096
    const dim3 blk(256);
    const float inv_sqrt_dh = 0.08838834764831845f;

    // C0: split inputs/weights
    {
        long long n;
        n = (long long)SB * SEQL * DMODEL;
        cvt_kernel<<<(unsigned)((n + 255) / 256), 256>>>(x, xh, xl, n);
        n = (long long)CLAT * DMODEL;
        cvt_kernel<<<(unsigned)((n + 255) / 256), 256>>>(Wd, wdh, wdl, n);
        n = (long long)HDTOT * DMODEL;
        cvt_kernel<<<(unsigned)((n + 255) / 256), 256>>>(Wq, wqh, wql, n);
        n = (long long)HDTOT * CLAT;
        cvt_kernel<<<(unsigned)((n + 255) / 256), 256>>>(Wuv, wuvh, wuvl, n);
        n = (long long)DMODEL * HDTOT;
        cvt_kernel<<<(unsigned)((n + 255) / 256), 256>>>(Wo, woh, wol, n);
    }
    // T2: wukT halves
    transpose_cvt_kernel<<<dim3(CLAT / 32, DHD / 32, NH), dim3(32, 8)>>>(
        Wuk, wukTh, wukTl, DHD, CLAT);

    // G1: latents = x @ Wd^T   (fp32 + halves)
    mma_gemm<0, 2><<<dim3(CLAT / BN, MROWS / BM, 1), blk, SMEM_BYTES>>>(
        xh, xl, wdh, wdl, lat, lath, latl, DMODEL, DMODEL, DMODEL, CLAT, 1.f);

    // T1: latT halves
    transpose_cvt_kernel<<<dim3(CLAT / 32, SEQL / 32, SB), dim3(32, 8)>>>(
        lat, latTh, latTl, SEQL, CLAT);

    // G2: q = x @ Wq^T  (halves out)
    mma_gemm<0, 1><<<dim3(HDTOT / BN, MROWS / BM, 1), blk, SMEM_BYTES>>>(
        xh, xl, wqh, wql, nullptr, qh, ql, DMODEL, DMODEL, DMODEL, HDTOT, 1.f);

    // G3: q_lat[z] = q_h @ wukT[h]^T   (K=128, halves out)
    mma_gemm<1, 1><<<dim3(CLAT / BN, SEQL / BM, SB * NH), blk, SMEM_BYTES>>>(
        qh, ql, wukTh, wukTl, nullptr, qlath, qlatl, DHD, HDTOT, DHD, CLAT, 1.f);

    // G4: scores = q_lat @ latents^T / sqrt(dh)  (causal, fp32 out)
    mma_gemm<2, 0><<<dim3(SEQL / BN, SEQL / BM, SB * NH), blk, SMEM_BYTES>>>(
        qlath, qlatl, lath, latl, sc, nullptr, nullptr, CLAT, CLAT, CLAT, SEQL, inv_sqrt_dh);

    // G5: softmax -> attn halves (single exp)
    softmax_kernel<<<(unsigned)((long long)SB * NH * SEQL / 8), 256>>>(sc, attnh, attnl);

    // G6: ctx = attn @ latT^T  (K_eff per row tile, halves out)
    mma_gemm<3, 1><<<dim3(CLAT / BN, SEQL / BM, SB * NH), blk, SMEM_BYTES>>>(
        attnh, attnl, latTh, latTl, nullptr, ctxh, ctxl, SEQL, SEQL, SEQL, CLAT, 1.f);

    // G7: v_h = ctx @ Wuv_h^T  (halves out)
    mma_gemm<4, 1><<<dim3(DHD / BN, SEQL / BM, SB * NH), blk, SMEM_BYTES>>>(
        ctxh, ctxl, wuvh, wuvl, nullptr, vh, vl, CLAT, CLAT, CLAT, HDTOT, 1.f);

    // G8: out = v @ Wo^T  (fp32 out)
    mma_gemm<0, 0><<<dim3(DMODEL / BN, MROWS / BM, 1), blk, SMEM_BYTES>>>(
        vh, vl, woh, wol, out, nullptr, nullptr, HDTOT, HDTOT, HDTOT, DMODEL, 1.f);
}

// round 12
// speedup vs baseline: 1.0609x; 1.0609x over previous
#include <cuda_runtime.h>
#include <cuda_fp16.h>
#include <math.h>
#include <stdint.h>

// ============================================================================
// MLA prefill — round 12: R11 + ldmatrix fragment loads.
// 48 LDS.32 per k16-step -> 12 ldmatrix.x4 (issue slots 96 -> 60/warp/step,
// smem port pressure /4). Same data, same mma order -> bit-identical results.
// ============================================================================

#define SB     2
#define SEQL   2048
#define DMODEL 2048
#define CLAT   512
#define NH     16
#define DHD    128
#define HDTOT  2048

// ---------------- scratch ----------------
__device__ __half g_xh [(size_t)SB * SEQL * DMODEL],  g_xl [(size_t)SB * SEQL * DMODEL];
__device__ __half g_wdh[(size_t)CLAT * DMODEL],       g_wdl[(size_t)CLAT * DMODEL];
__device__ __half g_wqh[(size_t)HDTOT * DMODEL],      g_wql[(size_t)HDTOT * DMODEL];
__device__ __half g_wuvh[(size_t)HDTOT * CLAT],       g_wuvl[(size_t)HDTOT * CLAT];
__device__ __half g_woh[(size_t)DMODEL * HDTOT],      g_wol[(size_t)DMODEL * HDTOT];
__device__ __half g_wukTh[(size_t)NH * CLAT * DHD],   g_wukTl[(size_t)NH * CLAT * DHD];
__device__ float  g_lat  [(size_t)SB * SEQL * CLAT];
__device__ __half g_lath [(size_t)SB * SEQL * CLAT],  g_latl [(size_t)SB * SEQL * CLAT];
__device__ __half g_latTh[(size_t)SB * CLAT * SEQL],  g_latTl[(size_t)SB * CLAT * SEQL];
__device__ __half g_qh   [(size_t)SB * SEQL * HDTOT], g_ql   [(size_t)SB * SEQL * HDTOT];
__device__ __half g_qlath[(size_t)SB * NH * SEQL * CLAT], g_qlatl[(size_t)SB * NH * SEQL * CLAT];
__device__ float  g_scores[(size_t)SB * NH * SEQL * SEQL];
__device__ __half g_attnh[(size_t)SB * NH * SEQL * SEQL], g_attnl[(size_t)SB * NH * SEQL * SEQL];
__device__ __half g_ctxh [(size_t)SB * NH * SEQL * CLAT], g_ctxl [(size_t)SB * NH * SEQL * CLAT];
__device__ __half g_vh   [(size_t)SB * SEQL * HDTOT], g_vl   [(size_t)SB * SEQL * HDTOT];

#define BM 128
#define BN 128
#define BK 32
#define ROWH 40      // smem row pitch in halves: ldmatrix-conflict-free (20r mod 32 bijective)
#define TILEH (BM * ROWH)
#define SMEM_BYTES (2 * 4 * TILEH * 2)          // 81920 B

// m16n8k16 fp16 mma, fp32 accumulate.
static __device__ __forceinline__ void mma_16816(float* d, const uint32_t* a,
                                                 const uint32_t* b) {
    asm("mma.sync.aligned.m16n8k16.row.col.f32.f16.f16.f32 "
        "{%0,%1,%2,%3}, {%4,%5,%6,%7}, {%8,%9}, {%0,%1,%2,%3};"
        : "+f"(d[0]), "+f"(d[1]), "+f"(d[2]), "+f"(d[3])
        : "r"(a[0]), "r"(a[1]), "r"(a[2]), "r"(a[3]), "r"(b[0]), "r"(b[1]));
}

// ldmatrix x4: 4 8x8 b16 matrices; lanes 0-7/8-15/16-23/24-31 give row addrs.
static __device__ __forceinline__ void ldsm_x4(uint32_t& r0, uint32_t& r1,
                                               uint32_t& r2, uint32_t& r3,
                                               uint32_t addr) {
    asm volatile("ldmatrix.sync.aligned.m8n8.x4.shared.b16 {%0,%1,%2,%3}, [%4];"
                 : "=r"(r0), "=r"(r1), "=r"(r2), "=r"(r3) : "r"(addr));
}

static __device__ __forceinline__ void fsplit(float f, __half& h, __half& l) {
    h = __float2half_rn(f);
    l = __float2half_rn(f - __half2float(h));
}

// cp.async one 128x32-half tile (8KB): 512 16B chunks, 2 per thread.
static __device__ __forceinline__ void pf_tile(__half* s, const __half* g, int ld, int tid) {
#pragma unroll
    for (int i = 0; i < 2; i++) {
        const int idx = tid + i * 256;
        const int r = idx >> 2;
        const int c = (idx & 3) << 3;
        unsigned dst = (unsigned)__cvta_generic_to_shared(s + r * ROWH + c);
        asm volatile("cp.async.cg.shared.global [%0], [%1], 16;"
                     :: "r"(dst), "l"(g + (long long)r * ld + c));
    }
}

// ---------------------------------------------------------------------------
// GEMM: C[128m,128n] = alpha * A @ B^T, A[M,K] hi/lo halves, B[N,K] hi/lo.
// MODE 0: plain. 1: G3. 2: G4 (causal skip). 3: G6 (K_eff). 4: G7.
// OUTK 0: fp32 C. 1: hi/lo half C. 2: both.
// 256 threads = 8 warps (2m x 4n); warp tile 64x32 = 4x4 m16n8k16 atoms.
// ---------------------------------------------------------------------------
template<int MODE, int OUTK>
__global__ void __launch_bounds__(256)
mma_gemm(const __half* __restrict__ Ah, const __half* __restrict__ Al,
         const __half* __restrict__ Bh, const __half* __restrict__ Bl,
         float* __restrict__ C, __half* __restrict__ Ch, __half* __restrict__ Cl,
         int K, int lda, int ldb, int ldc, float alpha)
{
    const int bn = blockIdx.x;
    const int bm = blockIdx.y;
    const int z  = blockIdx.z;

    if (MODE == 2 && bn > bm) return;

    long long aoff = 0, boff = 0, coff = 0;
    if (MODE == 1) {
        int b = z >> 4, h = z & 15;
        aoff = (long long)b * SEQL * HDTOT + (long long)h * DHD;
        boff = (long long)h * CLAT * DHD;
        coff = (long long)z * SEQL * CLAT;
    } else if (MODE == 2) {
        aoff = (long long)z * SEQL * CLAT;
        boff = (long long)(z >> 4) * SEQL * CLAT;
        coff = (long long)z * SEQL * SEQL;
    } else if (MODE == 3) {
        aoff = (long long)z * SEQL * SEQL;
        boff = (long long)(z >> 4) * CLAT * SEQL;
        coff = (long long)z * SEQL * CLAT;
    } else if (MODE == 4) {
        int b = z >> 4, h = z & 15;
        aoff = (long long)z * SEQL * CLAT;
        boff = (long long)h * DHD * CLAT;
        coff = (long long)b * SEQL * HDTOT + (long long)h * DHD;
    }

    const int Keff = (MODE == 3) ? min(K, (bm + 1) * BM) : K;
    const int nkt = Keff / BK;

    const __half* Abh = Ah + aoff + (long long)bm * BM * lda;
    const __half* Abl = Al + aoff + (long long)bm * BM * lda;
    const __half* Bbh = Bh + boff + (long long)bn * BN * ldb;
    const __half* Bbl = Bl + boff + (long long)bn * BN * ldb;
    const long long cbase = coff + (long long)bm * BM * ldc + (long long)bn * BN;

    extern __shared__ __half dynsm[];
#define SMT(buf, op) (dynsm + ((buf) * 4 + (op)) * TILEH)

    const int tid  = threadIdx.x;
    const int lane = tid & 31;
    const int w    = tid >> 5;
    const int mo = (w >> 2) * 64;
    const int no = (w & 3) * 32;
    const int g  = lane >> 2;
    const int t  = lane & 3;

    // ldmatrix per-lane address components (in halves)
    // A: matrices [r0-7,k0-7],[r8-15,k0-7],[r0-7,k8-15],[r8-15,k8-15]
    const int a_row  = mo + (lane & 7) + ((lane >> 3) & 1) * 8;
    const int a_koff = (lane >> 4) * 8;
    // B pair: matrices [n0-7,k0-7],[n0-7,k8-15],[n8-15,k0-7],[n8-15,k8-15]
    const int b_row  = no + (lane & 7) + ((lane >> 4) & 1) * 8;
    const int b_koff = ((lane >> 3) & 1) * 8;

    float acc[4][4][4];
#pragma unroll
    for (int mt = 0; mt < 4; mt++)
#pragma unroll
        for (int nt = 0; nt < 4; nt++)
#pragma unroll
            for (int e = 0; e < 4; e++) acc[mt][nt][e] = 0.f;

    pf_tile(SMT(0, 0), Abh, lda, tid);
    pf_tile(SMT(0, 1), Abl, lda, tid);
    pf_tile(SMT(0, 2), Bbh, ldb, tid);
    pf_tile(SMT(0, 3), Bbl, ldb, tid);
    asm volatile("cp.async.commit_group;");

    for (int kt = 0; kt < nkt; ++kt) {
        const int buf = kt & 1;
        if (kt + 1 < nkt) {
            const long long ko = (long long)(kt + 1) * BK;
            pf_tile(SMT(buf ^ 1, 0), Abh + ko, lda, tid);
            pf_tile(SMT(buf ^ 1, 1), Abl + ko, lda, tid);
            pf_tile(SMT(buf ^ 1, 2), Bbh + ko, ldb, tid);
            pf_tile(SMT(buf ^ 1, 3), Bbl + ko, ldb, tid);
            asm volatile("cp.async.commit_group;");
            asm volatile("cp.async.wait_group 1;");
        } else {
            asm volatile("cp.async.wait_group 0;");
        }
        __syncthreads();

        const uint32_t s_ah = (uint32_t)__cvta_generic_to_shared(SMT(buf, 0));
        const uint32_t s_al = (uint32_t)__cvta_generic_to_shared(SMT(buf, 1));
        const uint32_t s_bh = (uint32_t)__cvta_generic_to_shared(SMT(buf, 2));
        const uint32_t s_bl = (uint32_t)__cvta_generic_to_shared(SMT(buf, 3));

#pragma unroll
        for (int ks = 0; ks < 2; ks++) {        // two k16 steps per BK=32 tile
            const int kk = ks * 16;
            uint32_t ah[4][4], al[4][4], bh[4][2], bl[4][2];
#pragma unroll
            for (int mt = 0; mt < 4; mt++) {
                const uint32_t off = 2u * ((a_row + mt * 16) * ROWH + kk + a_koff);
                ldsm_x4(ah[mt][0], ah[mt][1], ah[mt][2], ah[mt][3], s_ah + off);
                ldsm_x4(al[mt][0], al[mt][1], al[mt][2], al[mt][3], s_al + off);
            }
#pragma unroll
            for (int p = 0; p < 2; p++) {       // nt pairs (2p, 2p+1)
                const uint32_t off = 2u * ((b_row + p * 16) * ROWH + kk + b_koff);
                ldsm_x4(bh[2 * p][0], bh[2 * p][1], bh[2 * p + 1][0], bh[2 * p + 1][1],
                        s_bh + off);
                ldsm_x4(bl[2 * p][0], bl[2 * p][1], bl[2 * p + 1][0], bl[2 * p + 1][1],
                        s_bl + off);
            }

            // pass-outer ordering; per-acc addition order: hh, hl, lh.
#pragma unroll
            for (int mt = 0; mt < 4; mt++)
#pragma unroll
                for (int nt = 0; nt < 4; nt++)
                    mma_16816(acc[mt][nt], ah[mt], bh[nt]);
#pragma unroll
            for (int mt = 0; mt < 4; mt++)
#pragma unroll
                for (int nt = 0; nt < 4; nt++)
                    mma_16816(acc[mt][nt], ah[mt], bl[nt]);
#pragma unroll
            for (int mt = 0; mt < 4; mt++)
#pragma unroll
                for (int nt = 0; nt < 4; nt++)
                    mma_16816(acc[mt][nt], al[mt], bh[nt]);
        }
        __syncthreads();
    }
#undef SMT

#pragma unroll
    for (int mt = 0; mt < 4; mt++) {
        const int r0 = mo + mt * 16 + g;
#pragma unroll
        for (int nt = 0; nt < 4; nt++) {
            const int ccol = no + nt * 8 + 2 * t;
            const long long i0 = cbase + (long long)r0 * ldc + ccol;
            const long long i1 = cbase + (long long)(r0 + 8) * ldc + ccol;
            float f0 = acc[mt][nt][0] * alpha, f1 = acc[mt][nt][1] * alpha;
            float f2 = acc[mt][nt][2] * alpha, f3 = acc[mt][nt][3] * alpha;
            if (OUTK == 0 || OUTK == 2) {
                *reinterpret_cast<float2*>(C + i0) = make_float2(f0, f1);
                *reinterpret_cast<float2*>(C + i1) = make_float2(f2, f3);
            }
            if (OUTK == 1 || OUTK == 2) {
                __half h0, l0, h1, l1, h2, l2, h3, l3;
                fsplit(f0, h0, l0); fsplit(f1, h1, l1);
                fsplit(f2, h2, l2); fsplit(f3, h3, l3);
                *reinterpret_cast<__half2*>(Ch + i0) = __halves2half2(h0, h1);
                *reinterpret_cast<__half2*>(Cl + i0) = __halves2half2(l0, l1);
                *reinterpret_cast<__half2*>(Ch + i1) = __halves2half2(h2, h3);
                *reinterpret_cast<__half2*>(Cl + i1) = __halves2half2(l2, l3);
            }
        }
    }
}

// ---------------------------------------------------------------------------
__global__ void cvt_kernel(const float* __restrict__ in, __half* __restrict__ oh,
                           __half* __restrict__ ol, long long n)
{
    long long i = (long long)blockIdx.x * blockDim.x + threadIdx.x;
    if (i < n) {
        __half h, l;
        fsplit(in[i], h, l);
        oh[i] = h; ol[i] = l;
    }
}

// ---------------------------------------------------------------------------
__global__ void transpose_cvt_kernel(const float* __restrict__ in,
                                     __half* __restrict__ oh, __half* __restrict__ ol,
                                     int R, int Cc)
{
    __shared__ float tsm[32][33];
    const int z = blockIdx.z;
    const int r0 = blockIdx.y * 32, c0 = blockIdx.x * 32;
    const float* I = in + (long long)z * R * Cc;
    const long long obase = (long long)z * R * Cc;
    const int tx = threadIdx.x, ty = threadIdx.y;
#pragma unroll
    for (int i = 0; i < 32; i += 8)
        tsm[ty + i][tx] = I[(long long)(r0 + ty + i) * Cc + c0 + tx];
    __syncthreads();
#pragma unroll
    for (int i = 0; i < 32; i += 8) {
        __half h, l;
        fsplit(tsm[tx][ty + i], h, l);
        long long o = obase + (long long)(c0 + ty + i) * R + r0 + tx;
        oh[o] = h; ol[o] = l;
    }
}

// ---------------------------------------------------------------------------
// Causal row softmax, single exp per element (store e back, renormalize).
// ---------------------------------------------------------------------------
__global__ void softmax_kernel(float* __restrict__ scores,
                               __half* __restrict__ ph, __half* __restrict__ pl)
{
    const int warp = threadIdx.x >> 5;
    const int lane = threadIdx.x & 31;
    const long long r = (long long)blockIdx.x * (blockDim.x >> 5) + warp;
    const int s = (int)(r & (SEQL - 1));
    const int len = s + 1;
    float* row = scores + r * SEQL;
    __half* rh = ph + r * SEQL;
    __half* rl = pl + r * SEQL;

    float mx = -INFINITY;
    for (int j = lane; j < len; j += 32) mx = fmaxf(mx, row[j]);
#pragma unroll
    for (int o = 16; o > 0; o >>= 1) mx = fmaxf(mx, __shfl_xor_sync(0xffffffffu, mx, o));

    float sum = 0.f;
    for (int j = lane; j < len; j += 32) {
        float e = __expf(row[j] - mx);
        row[j] = e;
        sum += e;
    }
#pragma unroll
    for (int o = 16; o > 0; o >>= 1) sum += __shfl_xor_sync(0xffffffffu, sum, o);

    const float inv = 1.0f / sum;
    for (int j = lane; j < len; j += 32) {
        float p = row[j] * inv;
        __half h, l;
        fsplit(p, h, l);
        rh[j] = h; rl[j] = l;
    }
    const int zend = ((s >> 7) + 1) << 7;
    for (int j = len + lane; j < zend; j += 32) {
        rh[j] = __float2half_rn(0.f); rl[j] = __float2half_rn(0.f);
    }
}

// ---------------------------------------------------------------------------
extern "C" void kernel_launch(void* const* d_in, const int* in_sizes, int n_in,
                              void* d_out, int out_size)
{
    const float* x   = (const float*)d_in[0];
    const float* Wd  = (const float*)d_in[1];
    const float* Wuk = (const float*)d_in[2];
    const float* Wuv = (const float*)d_in[3];
    const float* Wq  = (const float*)d_in[4];
    const float* Wo  = (const float*)d_in[5];
    float* out = (float*)d_out;

#define SYM(p, s) cudaGetSymbolAddress((void**)&p, s)
    __half *xh, *xl, *wdh, *wdl, *wqh, *wql, *wuvh, *wuvl, *woh, *wol, *wukTh, *wukTl;
    __half *lath, *latl, *latTh, *latTl, *qh, *ql, *qlath, *qlatl;
    __half *attnh, *attnl, *ctxh, *ctxl, *vh, *vl;
    float *lat, *sc;
    SYM(xh, g_xh); SYM(xl, g_xl); SYM(wdh, g_wdh); SYM(wdl, g_wdl);
    SYM(wqh, g_wqh); SYM(wql, g_wql); SYM(wuvh, g_wuvh); SYM(wuvl, g_wuvl);
    SYM(woh, g_woh); SYM(wol, g_wol); SYM(wukTh, g_wukTh); SYM(wukTl, g_wukTl);
    SYM(lat, g_lat); SYM(lath, g_lath); SYM(latl, g_latl);
    SYM(latTh, g_latTh); SYM(latTl, g_latTl);
    SYM(qh, g_qh); SYM(ql, g_ql); SYM(qlath, g_qlath); SYM(qlatl, g_qlatl);
    SYM(sc, g_scores); SYM(attnh, g_attnh); SYM(attnl, g_attnl);
    SYM(ctxh, g_ctxh); SYM(ctxl, g_ctxl); SYM(vh, g_vh); SYM(vl, g_vl);
#undef SYM

    static int attr_done = 0;
    if (!attr_done) {
        cudaFuncSetAttribute(mma_gemm<0, 0>, cudaFuncAttributeMaxDynamicSharedMemorySize, SMEM_BYTES);
        cudaFuncSetAttribute(mma_gemm<0, 1>, cudaFuncAttributeMaxDynamicSharedMemorySize, SMEM_BYTES);
        cudaFuncSetAttribute(mma_gemm<0, 2>, cudaFuncAttributeMaxDynamicSharedMemorySize, SMEM_BYTES);
        cudaFuncSetAttribute(mma_gemm<1, 1>, cudaFuncAttributeMaxDynamicSharedMemorySize, SMEM_BYTES);
        cudaFuncSetAttribute(mma_gemm<2, 0>, cudaFuncAttributeMaxDynamicSharedMemorySize, SMEM_BYTES);
        cudaFuncSetAttribute(mma_gemm<3, 1>, cudaFuncAttributeMaxDynamicSharedMemorySize, SMEM_BYTES);
        cudaFuncSetAttribute(mma_gemm<4, 1>, cudaFuncAttributeMaxDynamicSharedMemorySize, SMEM_BYTES);
        attr_done = 1;
    }

    const int MROWS = SB * SEQL;  // 4096
    const dim3 blk(256);
    const float inv_sqrt_dh = 0.08838834764831845f;

    // C0: split inputs/weights
    {
        long long n;
        n = (long long)SB * SEQL * DMODEL;
        cvt_kernel<<<(unsigned)((n + 255) / 256), 256>>>(x, xh, xl, n);
        n = (long long)CLAT * DMODEL;
        cvt_kernel<<<(unsigned)((n + 255) / 256), 256>>>(Wd, wdh, wdl, n);
        n = (long long)HDTOT * DMODEL;
        cvt_kernel<<<(unsigned)((n + 255) / 256), 256>>>(Wq, wqh, wql, n);
        n = (long long)HDTOT * CLAT;
        cvt_kernel<<<(unsigned)((n + 255) / 256), 256>>>(Wuv, wuvh, wuvl, n);
        n = (long long)DMODEL * HDTOT;
        cvt_kernel<<<(unsigned)((n + 255) / 256), 256>>>(Wo, woh, wol, n);
    }
    // T2: wukT halves
    transpose_cvt_kernel<<<dim3(CLAT / 32, DHD / 32, NH), dim3(32, 8)>>>(
        Wuk, wukTh, wukTl, DHD, CLAT);

    // G1: latents = x @ Wd^T   (fp32 + halves)
    mma_gemm<0, 2><<<dim3(CLAT / BN, MROWS / BM, 1), blk, SMEM_BYTES>>>(
        xh, xl, wdh, wdl, lat, lath, latl, DMODEL, DMODEL, DMODEL, CLAT, 1.f);

    // T1: latT halves
    transpose_cvt_kernel<<<dim3(CLAT / 32, SEQL / 32, SB), dim3(32, 8)>>>(
        lat, latTh, latTl, SEQL, CLAT);

    // G2: q = x @ Wq^T  (halves out)
    mma_gemm<0, 1><<<dim3(HDTOT / BN, MROWS / BM, 1), blk, SMEM_BYTES>>>(
        xh, xl, wqh, wql, nullptr, qh, ql, DMODEL, DMODEL, DMODEL, HDTOT, 1.f);

    // G3: q_lat[z] = q_h @ wukT[h]^T   (K=128, halves out)
    mma_gemm<1, 1><<<dim3(CLAT / BN, SEQL / BM, SB * NH), blk, SMEM_BYTES>>>(
        qh, ql, wukTh, wukTl, nullptr, qlath, qlatl, DHD, HDTOT, DHD, CLAT, 1.f);

    // G4: scores = q_lat @ latents^T / sqrt(dh)  (causal, fp32 out)
    mma_gemm<2, 0><<<dim3(SEQL / BN, SEQL / BM, SB * NH), blk, SMEM_BYTES>>>(
        qlath, qlatl, lath, latl, sc, nullptr, nullptr, CLAT, CLAT, CLAT, SEQL, inv_sqrt_dh);

    // G5: softmax -> attn halves (single exp)
    softmax_kernel<<<(unsigned)((long long)SB * NH * SEQL / 8), 256>>>(sc, attnh, attnl);

    // G6: ctx = attn @ latT^T  (K_eff per row tile, halves out)
    mma_gemm<3, 1><<<dim3(CLAT / BN, SEQL / BM, SB * NH), blk, SMEM_BYTES>>>(
        attnh, attnl, latTh, latTl, nullptr, ctxh, ctxl, SEQL, SEQL, SEQL, CLAT, 1.f);

    // G7: v_h = ctx @ Wuv_h^T  (halves out)
    mma_gemm<4, 1><<<dim3(DHD / BN, SEQL / BM, SB * NH), blk, SMEM_BYTES>>>(
        ctxh, ctxl, wuvh, wuvl, nullptr, vh, vl, CLAT, CLAT, CLAT, HDTOT, 1.f);

    // G8: out = v @ Wo^T  (fp32 out)
    mma_gemm<0, 0><<<dim3(DMODEL / BN, MROWS / BM, 1), blk, SMEM_BYTES>>>(
        vh, vl, woh, wol, out, nullptr, nullptr, HDTOT, HDTOT, HDTOT, DMODEL, 1.f);
}

// round 15
// speedup vs baseline: 1.1107x; 1.0469x over previous
#include <cuda_runtime.h>
#include <cuda_fp16.h>
#include <math.h>
#include <stdint.h>

// ============================================================================
// MLA prefill — round 15 (R13 resubmit #2; broker infra failures, kernel
// never executed): square warp grid (2x2, 64x64 warp tile, 128 thr).
// R12 analysis: mainloop is smem-BW bound (48KB/k16-step from cross-warp
// fragment redundancy (A x4, B x2) vs ~96cyc of HMMA). 2x2 grid cuts
// redundancy to (2,2): 32KB/k16 (-33%). Same block size, same math order ->
// rel_err bit-identical 2.109672e-05.
// ============================================================================

#define SB     2
#define SEQL   2048
#define DMODEL 2048
#define CLAT   512
#define NH     16
#define DHD    128
#define HDTOT  2048

// ---------------- scratch ----------------
__device__ __half g_xh [(size_t)SB * SEQL * DMODEL],  g_xl [(size_t)SB * SEQL * DMODEL];
__device__ __half g_wdh[(size_t)CLAT * DMODEL],       g_wdl[(size_t)CLAT * DMODEL];
__device__ __half g_wqh[(size_t)HDTOT * DMODEL],      g_wql[(size_t)HDTOT * DMODEL];
__device__ __half g_wuvh[(size_t)HDTOT * CLAT],       g_wuvl[(size_t)HDTOT * CLAT];
__device__ __half g_woh[(size_t)DMODEL * HDTOT],      g_wol[(size_t)DMODEL * HDTOT];
__device__ __half g_wukTh[(size_t)NH * CLAT * DHD],   g_wukTl[(size_t)NH * CLAT * DHD];
__device__ float  g_lat  [(size_t)SB * SEQL * CLAT];
__device__ __half g_lath [(size_t)SB * SEQL * CLAT],  g_latl [(size_t)SB * SEQL * CLAT];
__device__ __half g_latTh[(size_t)SB * CLAT * SEQL],  g_latTl[(size_t)SB * CLAT * SEQL];
__device__ __half g_qh   [(size_t)SB * SEQL * HDTOT], g_ql   [(size_t)SB * SEQL * HDTOT];
__device__ __half g_qlath[(size_t)SB * NH * SEQL * CLAT], g_qlatl[(size_t)SB * NH * SEQL * CLAT];
__device__ float  g_scores[(size_t)SB * NH * SEQL * SEQL];
__device__ __half g_attnh[(size_t)SB * NH * SEQL * SEQL], g_attnl[(size_t)SB * NH * SEQL * SEQL];
__device__ __half g_ctxh [(size_t)SB * NH * SEQL * CLAT], g_ctxl [(size_t)SB * NH * SEQL * CLAT];
__device__ __half g_vh   [(size_t)SB * SEQL * HDTOT], g_vl   [(size_t)SB * SEQL * HDTOT];

#define BM 128
#define BN 128
#define BK 32
#define ROWH 40      // smem row pitch in halves: ldmatrix-conflict-free (20r mod 32 bijective)
#define TILEH (BM * ROWH)
#define SMEM_BYTES (2 * 4 * TILEH * 2)          // 81920 B
#define NTHR 128                                 // 4 warps, 2m x 2n

// m16n8k16 fp16 mma, fp32 accumulate.
static __device__ __forceinline__ void mma_16816(float* d, const uint32_t* a,
                                                 const uint32_t* b) {
    asm("mma.sync.aligned.m16n8k16.row.col.f32.f16.f16.f32 "
        "{%0,%1,%2,%3}, {%4,%5,%6,%7}, {%8,%9}, {%0,%1,%2,%3};"
        : "+f"(d[0]), "+f"(d[1]), "+f"(d[2]), "+f"(d[3])
        : "r"(a[0]), "r"(a[1]), "r"(a[2]), "r"(a[3]), "r"(b[0]), "r"(b[1]));
}

static __device__ __forceinline__ void ldsm_x4(uint32_t& r0, uint32_t& r1,
                                               uint32_t& r2, uint32_t& r3,
                                               uint32_t addr) {
    asm volatile("ldmatrix.sync.aligned.m8n8.x4.shared.b16 {%0,%1,%2,%3}, [%4];"
                 : "=r"(r0), "=r"(r1), "=r"(r2), "=r"(r3) : "r"(addr));
}

static __device__ __forceinline__ void fsplit(float f, __half& h, __half& l) {
    h = __float2half_rn(f);
    l = __float2half_rn(f - __half2float(h));
}

// cp.async one 128x32-half tile (8KB): 512 16B chunks, 4 per thread (128 thr).
static __device__ __forceinline__ void pf_tile(__half* s, const __half* g, int ld, int tid) {
#pragma unroll
    for (int i = 0; i < 4; i++) {
        const int idx = tid + i * NTHR;     // 0..511
        const int r = idx >> 2;             // 0..127
        const int c = (idx & 3) << 3;       // 0,8,16,24 halves
        unsigned dst = (unsigned)__cvta_generic_to_shared(s + r * ROWH + c);
        asm volatile("cp.async.cg.shared.global [%0], [%1], 16;"
                     :: "r"(dst), "l"(g + (long long)r * ld + c));
    }
}

// ---------------------------------------------------------------------------
// GEMM: C[128m,128n] = alpha * A @ B^T, A[M,K] hi/lo halves, B[N,K] hi/lo.
// MODE 0: plain. 1: G3. 2: G4 (causal skip). 3: G6 (K_eff). 4: G7.
// OUTK 0: fp32 C. 1: hi/lo half C. 2: both.
// 128 threads = 4 warps (2m x 2n); warp tile 64x64 = 4x8 m16n8k16 atoms.
// ---------------------------------------------------------------------------
template<int MODE, int OUTK>
__global__ void __launch_bounds__(NTHR)
mma_gemm(const __half* __restrict__ Ah, const __half* __restrict__ Al,
         const __half* __restrict__ Bh, const __half* __restrict__ Bl,
         float* __restrict__ C, __half* __restrict__ Ch, __half* __restrict__ Cl,
         int K, int lda, int ldb, int ldc, float alpha)
{
    const int bn = blockIdx.x;
    const int bm = blockIdx.y;
    const int z  = blockIdx.z;

    if (MODE == 2 && bn > bm) return;

    long long aoff = 0, boff = 0, coff = 0;
    if (MODE == 1) {
        int b = z >> 4, h = z & 15;
        aoff = (long long)b * SEQL * HDTOT + (long long)h * DHD;
        boff = (long long)h * CLAT * DHD;
        coff = (long long)z * SEQL * CLAT;
    } else if (MODE == 2) {
        aoff = (long long)z * SEQL * CLAT;
        boff = (long long)(z >> 4) * SEQL * CLAT;
        coff = (long long)z * SEQL * SEQL;
    } else if (MODE == 3) {
        aoff = (long long)z * SEQL * SEQL;
        boff = (long long)(z >> 4) * CLAT * SEQL;
        coff = (long long)z * SEQL * CLAT;
    } else if (MODE == 4) {
        int b = z >> 4, h = z & 15;
        aoff = (long long)z * SEQL * CLAT;
        boff = (long long)h * DHD * CLAT;
        coff = (long long)b * SEQL * HDTOT + (long long)h * DHD;
    }

    const int Keff = (MODE == 3) ? min(K, (bm + 1) * BM) : K;
    const int nkt = Keff / BK;

    const __half* Abh = Ah + aoff + (long long)bm * BM * lda;
    const __half* Abl = Al + aoff + (long long)bm * BM * lda;
    const __half* Bbh = Bh + boff + (long long)bn * BN * ldb;
    const __half* Bbl = Bl + boff + (long long)bn * BN * ldb;
    const long long cbase = coff + (long long)bm * BM * ldc + (long long)bn * BN;

    extern __shared__ __half dynsm[];
#define SMT(buf, op) (dynsm + ((buf) * 4 + (op)) * TILEH)

    const int tid  = threadIdx.x;
    const int lane = tid & 31;
    const int w    = tid >> 5;          // 0..3
    const int mo = (w >> 1) * 64;       // 0 / 64
    const int no = (w & 1) * 64;        // 0 / 64
    const int g  = lane >> 2;
    const int t  = lane & 3;

    // ldmatrix per-lane address components (in halves)
    const int a_row  = mo + (lane & 7) + ((lane >> 3) & 1) * 8;
    const int a_koff = (lane >> 4) * 8;
    const int b_row  = no + (lane & 7) + ((lane >> 4) & 1) * 8;
    const int b_koff = ((lane >> 3) & 1) * 8;

    float acc[4][8][4];
#pragma unroll
    for (int mt = 0; mt < 4; mt++)
#pragma unroll
        for (int nt = 0; nt < 8; nt++)
#pragma unroll
            for (int e = 0; e < 4; e++) acc[mt][nt][e] = 0.f;

    pf_tile(SMT(0, 0), Abh, lda, tid);
    pf_tile(SMT(0, 1), Abl, lda, tid);
    pf_tile(SMT(0, 2), Bbh, ldb, tid);
    pf_tile(SMT(0, 3), Bbl, ldb, tid);
    asm volatile("cp.async.commit_group;");

    for (int kt = 0; kt < nkt; ++kt) {
        const int buf = kt & 1;
        if (kt + 1 < nkt) {
            const long long ko = (long long)(kt + 1) * BK;
            pf_tile(SMT(buf ^ 1, 0), Abh + ko, lda, tid);
            pf_tile(SMT(buf ^ 1, 1), Abl + ko, lda, tid);
            pf_tile(SMT(buf ^ 1, 2), Bbh + ko, ldb, tid);
            pf_tile(SMT(buf ^ 1, 3), Bbl + ko, ldb, tid);
            asm volatile("cp.async.commit_group;");
            asm volatile("cp.async.wait_group 1;");
        } else {
            asm volatile("cp.async.wait_group 0;");
        }
        __syncthreads();

        const uint32_t s_ah = (uint32_t)__cvta_generic_to_shared(SMT(buf, 0));
        const uint32_t s_al = (uint32_t)__cvta_generic_to_shared(SMT(buf, 1));
        const uint32_t s_bh = (uint32_t)__cvta_generic_to_shared(SMT(buf, 2));
        const uint32_t s_bl = (uint32_t)__cvta_generic_to_shared(SMT(buf, 3));

#pragma unroll
        for (int ks = 0; ks < 2; ks++) {        // two k16 steps per BK=32 tile
            const int kk = ks * 16;
            uint32_t ah[4][4], al[4][4], bh[8][2], bl[8][2];
#pragma unroll
            for (int mt = 0; mt < 4; mt++) {
                const uint32_t off = 2u * ((a_row + mt * 16) * ROWH + kk + a_koff);
                ldsm_x4(ah[mt][0], ah[mt][1], ah[mt][2], ah[mt][3], s_ah + off);
                ldsm_x4(al[mt][0], al[mt][1], al[mt][2], al[mt][3], s_al + off);
            }
#pragma unroll
            for (int p = 0; p < 4; p++) {       // nt pairs (2p, 2p+1)
                const uint32_t off = 2u * ((b_row + p * 16) * ROWH + kk + b_koff);
                ldsm_x4(bh[2 * p][0], bh[2 * p][1], bh[2 * p + 1][0], bh[2 * p + 1][1],
                        s_bh + off);
                ldsm_x4(bl[2 * p][0], bl[2 * p][1], bl[2 * p + 1][0], bl[2 * p + 1][1],
                        s_bl + off);
            }

            // pass-outer ordering; per-acc addition order: hh, hl, lh.
#pragma unroll
            for (int mt = 0; mt < 4; mt++)
#pragma unroll
                for (int nt = 0; nt < 8; nt++)
                    mma_16816(acc[mt][nt], ah[mt], bh[nt]);
#pragma unroll
            for (int mt = 0; mt < 4; mt++)
#pragma unroll
                for (int nt = 0; nt < 8; nt++)
                    mma_16816(acc[mt][nt], ah[mt], bl[nt]);
#pragma unroll
            for (int mt = 0; mt < 4; mt++)
#pragma unroll
                for (int nt = 0; nt < 8; nt++)
                    mma_16816(acc[mt][nt], al[mt], bh[nt]);
        }
        __syncthreads();
    }
#undef SMT

#pragma unroll
    for (int mt = 0; mt < 4; mt++) {
        const int r0 = mo + mt * 16 + g;
#pragma unroll
        for (int nt = 0; nt < 8; nt++) {
            const int ccol = no + nt * 8 + 2 * t;
            const long long i0 = cbase + (long long)r0 * ldc + ccol;
            const long long i1 = cbase + (long long)(r0 + 8) * ldc + ccol;
            float f0 = acc[mt][nt][0] * alpha, f1 = acc[mt][nt][1] * alpha;
            float f2 = acc[mt][nt][2] * alpha, f3 = acc[mt][nt][3] * alpha;
            if (OUTK == 0 || OUTK == 2) {
                *reinterpret_cast<float2*>(C + i0) = make_float2(f0, f1);
                *reinterpret_cast<float2*>(C + i1) = make_float2(f2, f3);
            }
            if (OUTK == 1 || OUTK == 2) {
                __half h0, l0, h1, l1, h2, l2, h3, l3;
                fsplit(f0, h0, l0); fsplit(f1, h1, l1);
                fsplit(f2, h2, l2); fsplit(f3, h3, l3);
                *reinterpret_cast<__half2*>(Ch + i0) = __halves2half2(h0, h1);
                *reinterpret_cast<__half2*>(Cl + i0) = __halves2half2(l0, l1);
                *reinterpret_cast<__half2*>(Ch + i1) = __halves2half2(h2, h3);
                *reinterpret_cast<__half2*>(Cl + i1) = __halves2half2(l2, l3);
            }
        }
    }
}

// ---------------------------------------------------------------------------
__global__ void cvt_kernel(const float* __restrict__ in, __half* __restrict__ oh,
                           __half* __restrict__ ol, long long n)
{
    long long i = (long long)blockIdx.x * blockDim.x + threadIdx.x;
    if (i < n) {
        __half h, l;
        fsplit(in[i], h, l);
        oh[i] = h; ol[i] = l;
    }
}

// ---------------------------------------------------------------------------
__global__ void transpose_cvt_kernel(const float* __restrict__ in,
                                     __half* __restrict__ oh, __half* __restrict__ ol,
                                     int R, int Cc)
{
    __shared__ float tsm[32][33];
    const int z = blockIdx.z;
    const int r0 = blockIdx.y * 32, c0 = blockIdx.x * 32;
    const float* I = in + (long long)z * R * Cc;
    const long long obase = (long long)z * R * Cc;
    const int tx = threadIdx.x, ty = threadIdx.y;
#pragma unroll
    for (int i = 0; i < 32; i += 8)
        tsm[ty + i][tx] = I[(long long)(r0 + ty + i) * Cc + c0 + tx];
    __syncthreads();
#pragma unroll
    for (int i = 0; i < 32; i += 8) {
        __half h, l;
        fsplit(tsm[tx][ty + i], h, l);
        long long o = obase + (long long)(c0 + ty + i) * R + r0 + tx;
        oh[o] = h; ol[o] = l;
    }
}

// ---------------------------------------------------------------------------
// Causal row softmax, single exp per element (store e back, renormalize).
// ---------------------------------------------------------------------------
__global__ void softmax_kernel(float* __restrict__ scores,
                               __half* __restrict__ ph, __half* __restrict__ pl)
{
    const int warp = threadIdx.x >> 5;
    const int lane = threadIdx.x & 31;
    const long long r = (long long)blockIdx.x * (blockDim.x >> 5) + warp;
    const int s = (int)(r & (SEQL - 1));
    const int len = s + 1;
    float* row = scores + r * SEQL;
    __half* rh = ph + r * SEQL;
    __half* rl = pl + r * SEQL;

    float mx = -INFINITY;
    for (int j = lane; j < len; j += 32) mx = fmaxf(mx, row[j]);
#pragma unroll
    for (int o = 16; o > 0; o >>= 1) mx = fmaxf(mx, __shfl_xor_sync(0xffffffffu, mx, o));

    float sum = 0.f;
    for (int j = lane; j < len; j += 32) {
        float e = __expf(row[j] - mx);
        row[j] = e;
        sum += e;
    }
#pragma unroll
    for (int o = 16; o > 0; o >>= 1) sum += __shfl_xor_sync(0xffffffffu, sum, o);

    const float inv = 1.0f / sum;
    for (int j = lane; j < len; j += 32) {
        float p = row[j] * inv;
        __half h, l;
        fsplit(p, h, l);
        rh[j] = h; rl[j] = l;
    }
    const int zend = ((s >> 7) + 1) << 7;
    for (int j = len + lane; j < zend; j += 32) {
        rh[j] = __float2half_rn(0.f); rl[j] = __float2half_rn(0.f);
    }
}

// ---------------------------------------------------------------------------
extern "C" void kernel_launch(void* const* d_in, const int* in_sizes, int n_in,
                              void* d_out, int out_size)
{
    const float* x   = (const float*)d_in[0];
    const float* Wd  = (const float*)d_in[1];
    const float* Wuk = (const float*)d_in[2];
    const float* Wuv = (const float*)d_in[3];
    const float* Wq  = (const float*)d_in[4];
    const float* Wo  = (const float*)d_in[5];
    float* out = (float*)d_out;

#define SYM(p, s) cudaGetSymbolAddress((void**)&p, s)
    __half *xh, *xl, *wdh, *wdl, *wqh, *wql, *wuvh, *wuvl, *woh, *wol, *wukTh, *wukTl;
    __half *lath, *latl, *latTh, *latTl, *qh, *ql, *qlath, *qlatl;
    __half *attnh, *attnl, *ctxh, *ctxl, *vh, *vl;
    float *lat, *sc;
    SYM(xh, g_xh); SYM(xl, g_xl); SYM(wdh, g_wdh); SYM(wdl, g_wdl);
    SYM(wqh, g_wqh); SYM(wql, g_wql); SYM(wuvh, g_wuvh); SYM(wuvl, g_wuvl);
    SYM(woh, g_woh); SYM(wol, g_wol); SYM(wukTh, g_wukTh); SYM(wukTl, g_wukTl);
    SYM(lat, g_lat); SYM(lath, g_lath); SYM(latl, g_latl);
    SYM(latTh, g_latTh); SYM(latTl, g_latTl);
    SYM(qh, g_qh); SYM(ql, g_ql); SYM(qlath, g_qlath); SYM(qlatl, g_qlatl);
    SYM(sc, g_scores); SYM(attnh, g_attnh); SYM(attnl, g_attnl);
    SYM(ctxh, g_ctxh); SYM(ctxl, g_ctxl); SYM(vh, g_vh); SYM(vl, g_vl);
#undef SYM

    static int attr_done = 0;
    if (!attr_done) {
        cudaFuncSetAttribute(mma_gemm<0, 0>, cudaFuncAttributeMaxDynamicSharedMemorySize, SMEM_BYTES);
        cudaFuncSetAttribute(mma_gemm<0, 1>, cudaFuncAttributeMaxDynamicSharedMemorySize, SMEM_BYTES);
        cudaFuncSetAttribute(mma_gemm<0, 2>, cudaFuncAttributeMaxDynamicSharedMemorySize, SMEM_BYTES);
        cudaFuncSetAttribute(mma_gemm<1, 1>, cudaFuncAttributeMaxDynamicSharedMemorySize, SMEM_BYTES);
        cudaFuncSetAttribute(mma_gemm<2, 0>, cudaFuncAttributeMaxDynamicSharedMemorySize, SMEM_BYTES);
        cudaFuncSetAttribute(mma_gemm<3, 1>, cudaFuncAttributeMaxDynamicSharedMemorySize, SMEM_BYTES);
        cudaFuncSetAttribute(mma_gemm<4, 1>, cudaFuncAttributeMaxDynamicSharedMemorySize, SMEM_BYTES);
        attr_done = 1;
    }

    const int MROWS = SB * SEQL;  // 4096
    const dim3 blk(NTHR);
    const float inv_sqrt_dh = 0.08838834764831845f;

    // C0: split inputs/weights
    {
        long long n;
        n = (long long)SB * SEQL * DMODEL;
        cvt_kernel<<<(unsigned)((n + 255) / 256), 256>>>(x, xh, xl, n);
        n = (long long)CLAT * DMODEL;
        cvt_kernel<<<(unsigned)((n + 255) / 256), 256>>>(Wd, wdh, wdl, n);
        n = (long long)HDTOT * DMODEL;
        cvt_kernel<<<(unsigned)((n + 255) / 256), 256>>>(Wq, wqh, wql, n);
        n = (long long)HDTOT * CLAT;
        cvt_kernel<<<(unsigned)((n + 255) / 256), 256>>>(Wuv, wuvh, wuvl, n);
        n = (long long)DMODEL * HDTOT;
        cvt_kernel<<<(unsigned)((n + 255) / 256), 256>>>(Wo, woh, wol, n);
    }
    // T2: wukT halves
    transpose_cvt_kernel<<<dim3(CLAT / 32, DHD / 32, NH), dim3(32, 8)>>>(
        Wuk, wukTh, wukTl, DHD, CLAT);

    // G1: latents = x @ Wd^T   (fp32 + halves)
    mma_gemm<0, 2><<<dim3(CLAT / BN, MROWS / BM, 1), blk, SMEM_BYTES>>>(
        xh, xl, wdh, wdl, lat, lath, latl, DMODEL, DMODEL, DMODEL, CLAT, 1.f);

    // T1: latT halves
    transpose_cvt_kernel<<<dim3(CLAT / 32, SEQL / 32, SB), dim3(32, 8)>>>(
        lat, latTh, latTl, SEQL, CLAT);

    // G2: q = x @ Wq^T  (halves out)
    mma_gemm<0, 1><<<dim3(HDTOT / BN, MROWS / BM, 1), blk, SMEM_BYTES>>>(
        xh, xl, wqh, wql, nullptr, qh, ql, DMODEL, DMODEL, DMODEL, HDTOT, 1.f);

    // G3: q_lat[z] = q_h @ wukT[h]^T   (K=128, halves out)
    mma_gemm<1, 1><<<dim3(CLAT / BN, SEQL / BM, SB * NH), blk, SMEM_BYTES>>>(
        qh, ql, wukTh, wukTl, nullptr, qlath, qlatl, DHD, HDTOT, DHD, CLAT, 1.f);

    // G4: scores = q_lat @ latents^T / sqrt(dh)  (causal, fp32 out)
    mma_gemm<2, 0><<<dim3(SEQL / BN, SEQL / BM, SB * NH), blk, SMEM_BYTES>>>(
        qlath, qlatl, lath, latl, sc, nullptr, nullptr, CLAT, CLAT, CLAT, SEQL, inv_sqrt_dh);

    // G5: softmax -> attn halves (single exp)
    softmax_kernel<<<(unsigned)((long long)SB * NH * SEQL / 8), 256>>>(sc, attnh, attnl);

    // G6: ctx = attn @ latT^T  (K_eff per row tile, halves out)
    mma_gemm<3, 1><<<dim3(CLAT / BN, SEQL / BM, SB * NH), blk, SMEM_BYTES>>>(
        attnh, attnl, latTh, latTl, nullptr, ctxh, ctxl, SEQL, SEQL, SEQL, CLAT, 1.f);

    // G7: v_h = ctx @ Wuv_h^T  (halves out)
    mma_gemm<4, 1><<<dim3(DHD / BN, SEQL / BM, SB * NH), blk, SMEM_BYTES>>>(
        ctxh, ctxl, wuvh, wuvl, nullptr, vh, vl, CLAT, CLAT, CLAT, HDTOT, 1.f);

    // G8: out = v @ Wo^T  (fp32 out)
    mma_gemm<0, 0><<<dim3(DMODEL / BN, MROWS / BM, 1), blk, SMEM_BYTES>>>(
        vh, vl, woh, wol, out, nullptr, nullptr, HDTOT, HDTOT, HDTOT, DMODEL, 1.f);
}

// round 16
// speedup vs baseline: 1.1243x; 1.0122x over previous
#include <cuda_runtime.h>
#include <cuda_fp16.h>
#include <math.h>
#include <stdint.h>

// ============================================================================
// MLA prefill — round 16: R15 + register-resident softmax.
// GEMMs at the mma.sync throughput ceiling (R12/R15 both gave ~5%); the
// remaining fat is non-GEMM time. Softmax now reads each score row ONCE into
// registers (<=64 floats/lane), does max/exp/sum in regs, writes halves once:
// 1.6GB -> 0.8GB traffic, no fp32 writeback. Identical arithmetic order ->
// rel_err bit-identical 2.109672e-05.
// ============================================================================

#define SB     2
#define SEQL   2048
#define DMODEL 2048
#define CLAT   512
#define NH     16
#define DHD    128
#define HDTOT  2048

// ---------------- scratch ----------------
__device__ __half g_xh [(size_t)SB * SEQL * DMODEL],  g_xl [(size_t)SB * SEQL * DMODEL];
__device__ __half g_wdh[(size_t)CLAT * DMODEL],       g_wdl[(size_t)CLAT * DMODEL];
__device__ __half g_wqh[(size_t)HDTOT * DMODEL],      g_wql[(size_t)HDTOT * DMODEL];
__device__ __half g_wuvh[(size_t)HDTOT * CLAT],       g_wuvl[(size_t)HDTOT * CLAT];
__device__ __half g_woh[(size_t)DMODEL * HDTOT],      g_wol[(size_t)DMODEL * HDTOT];
__device__ __half g_wukTh[(size_t)NH * CLAT * DHD],   g_wukTl[(size_t)NH * CLAT * DHD];
__device__ float  g_lat  [(size_t)SB * SEQL * CLAT];
__device__ __half g_lath [(size_t)SB * SEQL * CLAT],  g_latl [(size_t)SB * SEQL * CLAT];
__device__ __half g_latTh[(size_t)SB * CLAT * SEQL],  g_latTl[(size_t)SB * CLAT * SEQL];
__device__ __half g_qh   [(size_t)SB * SEQL * HDTOT], g_ql   [(size_t)SB * SEQL * HDTOT];
__device__ __half g_qlath[(size_t)SB * NH * SEQL * CLAT], g_qlatl[(size_t)SB * NH * SEQL * CLAT];
__device__ float  g_scores[(size_t)SB * NH * SEQL * SEQL];
__device__ __half g_attnh[(size_t)SB * NH * SEQL * SEQL], g_attnl[(size_t)SB * NH * SEQL * SEQL];
__device__ __half g_ctxh [(size_t)SB * NH * SEQL * CLAT], g_ctxl [(size_t)SB * NH * SEQL * CLAT];
__device__ __half g_vh   [(size_t)SB * SEQL * HDTOT], g_vl   [(size_t)SB * SEQL * HDTOT];

#define BM 128
#define BN 128
#define BK 32
#define ROWH 40      // smem row pitch in halves: ldmatrix-conflict-free (20r mod 32 bijective)
#define TILEH (BM * ROWH)
#define SMEM_BYTES (2 * 4 * TILEH * 2)          // 81920 B
#define NTHR 128                                 // 4 warps, 2m x 2n

// m16n8k16 fp16 mma, fp32 accumulate.
static __device__ __forceinline__ void mma_16816(float* d, const uint32_t* a,
                                                 const uint32_t* b) {
    asm("mma.sync.aligned.m16n8k16.row.col.f32.f16.f16.f32 "
        "{%0,%1,%2,%3}, {%4,%5,%6,%7}, {%8,%9}, {%0,%1,%2,%3};"
        : "+f"(d[0]), "+f"(d[1]), "+f"(d[2]), "+f"(d[3])
        : "r"(a[0]), "r"(a[1]), "r"(a[2]), "r"(a[3]), "r"(b[0]), "r"(b[1]));
}

static __device__ __forceinline__ void ldsm_x4(uint32_t& r0, uint32_t& r1,
                                               uint32_t& r2, uint32_t& r3,
                                               uint32_t addr) {
    asm volatile("ldmatrix.sync.aligned.m8n8.x4.shared.b16 {%0,%1,%2,%3}, [%4];"
                 : "=r"(r0), "=r"(r1), "=r"(r2), "=r"(r3) : "r"(addr));
}

static __device__ __forceinline__ void fsplit(float f, __half& h, __half& l) {
    h = __float2half_rn(f);
    l = __float2half_rn(f - __half2float(h));
}

// cp.async one 128x32-half tile (8KB): 512 16B chunks, 4 per thread (128 thr).
static __device__ __forceinline__ void pf_tile(__half* s, const __half* g, int ld, int tid) {
#pragma unroll
    for (int i = 0; i < 4; i++) {
        const int idx = tid + i * NTHR;     // 0..511
        const int r = idx >> 2;             // 0..127
        const int c = (idx & 3) << 3;       // 0,8,16,24 halves
        unsigned dst = (unsigned)__cvta_generic_to_shared(s + r * ROWH + c);
        asm volatile("cp.async.cg.shared.global [%0], [%1], 16;"
                     :: "r"(dst), "l"(g + (long long)r * ld + c));
    }
}

// ---------------------------------------------------------------------------
// GEMM: C[128m,128n] = alpha * A @ B^T, A[M,K] hi/lo halves, B[N,K] hi/lo.
// MODE 0: plain. 1: G3. 2: G4 (causal skip). 3: G6 (K_eff). 4: G7.
// OUTK 0: fp32 C. 1: hi/lo half C. 2: both.
// 128 threads = 4 warps (2m x 2n); warp tile 64x64 = 4x8 m16n8k16 atoms.
// ---------------------------------------------------------------------------
template<int MODE, int OUTK>
__global__ void __launch_bounds__(NTHR)
mma_gemm(const __half* __restrict__ Ah, const __half* __restrict__ Al,
         const __half* __restrict__ Bh, const __half* __restrict__ Bl,
         float* __restrict__ C, __half* __restrict__ Ch, __half* __restrict__ Cl,
         int K, int lda, int ldb, int ldc, float alpha)
{
    const int bn = blockIdx.x;
    const int bm = blockIdx.y;
    const int z  = blockIdx.z;

    if (MODE == 2 && bn > bm) return;

    long long aoff = 0, boff = 0, coff = 0;
    if (MODE == 1) {
        int b = z >> 4, h = z & 15;
        aoff = (long long)b * SEQL * HDTOT + (long long)h * DHD;
        boff = (long long)h * CLAT * DHD;
        coff = (long long)z * SEQL * CLAT;
    } else if (MODE == 2) {
        aoff = (long long)z * SEQL * CLAT;
        boff = (long long)(z >> 4) * SEQL * CLAT;
        coff = (long long)z * SEQL * SEQL;
    } else if (MODE == 3) {
        aoff = (long long)z * SEQL * SEQL;
        boff = (long long)(z >> 4) * CLAT * SEQL;
        coff = (long long)z * SEQL * CLAT;
    } else if (MODE == 4) {
        int b = z >> 4, h = z & 15;
        aoff = (long long)z * SEQL * CLAT;
        boff = (long long)h * DHD * CLAT;
        coff = (long long)b * SEQL * HDTOT + (long long)h * DHD;
    }

    const int Keff = (MODE == 3) ? min(K, (bm + 1) * BM) : K;
    const int nkt = Keff / BK;

    const __half* Abh = Ah + aoff + (long long)bm * BM * lda;
    const __half* Abl = Al + aoff + (long long)bm * BM * lda;
    const __half* Bbh = Bh + boff + (long long)bn * BN * ldb;
    const __half* Bbl = Bl + boff + (long long)bn * BN * ldb;
    const long long cbase = coff + (long long)bm * BM * ldc + (long long)bn * BN;

    extern __shared__ __half dynsm[];
#define SMT(buf, op) (dynsm + ((buf) * 4 + (op)) * TILEH)

    const int tid  = threadIdx.x;
    const int lane = tid & 31;
    const int w    = tid >> 5;          // 0..3
    const int mo = (w >> 1) * 64;       // 0 / 64
    const int no = (w & 1) * 64;        // 0 / 64
    const int g  = lane >> 2;
    const int t  = lane & 3;

    // ldmatrix per-lane address components (in halves)
    const int a_row  = mo + (lane & 7) + ((lane >> 3) & 1) * 8;
    const int a_koff = (lane >> 4) * 8;
    const int b_row  = no + (lane & 7) + ((lane >> 4) & 1) * 8;
    const int b_koff = ((lane >> 3) & 1) * 8;

    float acc[4][8][4];
#pragma unroll
    for (int mt = 0; mt < 4; mt++)
#pragma unroll
        for (int nt = 0; nt < 8; nt++)
#pragma unroll
            for (int e = 0; e < 4; e++) acc[mt][nt][e] = 0.f;

    pf_tile(SMT(0, 0), Abh, lda, tid);
    pf_tile(SMT(0, 1), Abl, lda, tid);
    pf_tile(SMT(0, 2), Bbh, ldb, tid);
    pf_tile(SMT(0, 3), Bbl, ldb, tid);
    asm volatile("cp.async.commit_group;");

    for (int kt = 0; kt < nkt; ++kt) {
        const int buf = kt & 1;
        if (kt + 1 < nkt) {
            const long long ko = (long long)(kt + 1) * BK;
            pf_tile(SMT(buf ^ 1, 0), Abh + ko, lda, tid);
            pf_tile(SMT(buf ^ 1, 1), Abl + ko, lda, tid);
            pf_tile(SMT(buf ^ 1, 2), Bbh + ko, ldb, tid);
            pf_tile(SMT(buf ^ 1, 3), Bbl + ko, ldb, tid);
            asm volatile("cp.async.commit_group;");
            asm volatile("cp.async.wait_group 1;");
        } else {
            asm volatile("cp.async.wait_group 0;");
        }
        __syncthreads();

        const uint32_t s_ah = (uint32_t)__cvta_generic_to_shared(SMT(buf, 0));
        const uint32_t s_al = (uint32_t)__cvta_generic_to_shared(SMT(buf, 1));
        const uint32_t s_bh = (uint32_t)__cvta_generic_to_shared(SMT(buf, 2));
        const uint32_t s_bl = (uint32_t)__cvta_generic_to_shared(SMT(buf, 3));

#pragma unroll
        for (int ks = 0; ks < 2; ks++) {        // two k16 steps per BK=32 tile
            const int kk = ks * 16;
            uint32_t ah[4][4], al[4][4], bh[8][2], bl[8][2];
#pragma unroll
            for (int mt = 0; mt < 4; mt++) {
                const uint32_t off = 2u * ((a_row + mt * 16) * ROWH + kk + a_koff);
                ldsm_x4(ah[mt][0], ah[mt][1], ah[mt][2], ah[mt][3], s_ah + off);
                ldsm_x4(al[mt][0], al[mt][1], al[mt][2], al[mt][3], s_al + off);
            }
#pragma unroll
            for (int p = 0; p < 4; p++) {       // nt pairs (2p, 2p+1)
                const uint32_t off = 2u * ((b_row + p * 16) * ROWH + kk + b_koff);
                ldsm_x4(bh[2 * p][0], bh[2 * p][1], bh[2 * p + 1][0], bh[2 * p + 1][1],
                        s_bh + off);
                ldsm_x4(bl[2 * p][0], bl[2 * p][1], bl[2 * p + 1][0], bl[2 * p + 1][1],
                        s_bl + off);
            }

            // pass-outer ordering; per-acc addition order: hh, hl, lh.
#pragma unroll
            for (int mt = 0; mt < 4; mt++)
#pragma unroll
                for (int nt = 0; nt < 8; nt++)
                    mma_16816(acc[mt][nt], ah[mt], bh[nt]);
#pragma unroll
            for (int mt = 0; mt < 4; mt++)
#pragma unroll
                for (int nt = 0; nt < 8; nt++)
                    mma_16816(acc[mt][nt], ah[mt], bl[nt]);
#pragma unroll
            for (int mt = 0; mt < 4; mt++)
#pragma unroll
                for (int nt = 0; nt < 8; nt++)
                    mma_16816(acc[mt][nt], al[mt], bh[nt]);
        }
        __syncthreads();
    }
#undef SMT

#pragma unroll
    for (int mt = 0; mt < 4; mt++) {
        const int r0 = mo + mt * 16 + g;
#pragma unroll
        for (int nt = 0; nt < 8; nt++) {
            const int ccol = no + nt * 8 + 2 * t;
            const long long i0 = cbase + (long long)r0 * ldc + ccol;
            const long long i1 = cbase + (long long)(r0 + 8) * ldc + ccol;
            float f0 = acc[mt][nt][0] * alpha, f1 = acc[mt][nt][1] * alpha;
            float f2 = acc[mt][nt][2] * alpha, f3 = acc[mt][nt][3] * alpha;
            if (OUTK == 0 || OUTK == 2) {
                *reinterpret_cast<float2*>(C + i0) = make_float2(f0, f1);
                *reinterpret_cast<float2*>(C + i1) = make_float2(f2, f3);
            }
            if (OUTK == 1 || OUTK == 2) {
                __half h0, l0, h1, l1, h2, l2, h3, l3;
                fsplit(f0, h0, l0); fsplit(f1, h1, l1);
                fsplit(f2, h2, l2); fsplit(f3, h3, l3);
                *reinterpret_cast<__half2*>(Ch + i0) = __halves2half2(h0, h1);
                *reinterpret_cast<__half2*>(Cl + i0) = __halves2half2(l0, l1);
                *reinterpret_cast<__half2*>(Ch + i1) = __halves2half2(h2, h3);
                *reinterpret_cast<__half2*>(Cl + i1) = __halves2half2(l2, l3);
            }
        }
    }
}

// ---------------------------------------------------------------------------
__global__ void cvt_kernel(const float* __restrict__ in, __half* __restrict__ oh,
                           __half* __restrict__ ol, long long n)
{
    long long i = (long long)blockIdx.x * blockDim.x + threadIdx.x;
    if (i < n) {
        __half h, l;
        fsplit(in[i], h, l);
        oh[i] = h; ol[i] = l;
    }
}

// ---------------------------------------------------------------------------
__global__ void transpose_cvt_kernel(const float* __restrict__ in,
                                     __half* __restrict__ oh, __half* __restrict__ ol,
                                     int R, int Cc)
{
    __shared__ float tsm[32][33];
    const int z = blockIdx.z;
    const int r0 = blockIdx.y * 32, c0 = blockIdx.x * 32;
    const float* I = in + (long long)z * R * Cc;
    const long long obase = (long long)z * R * Cc;
    const int tx = threadIdx.x, ty = threadIdx.y;
#pragma unroll
    for (int i = 0; i < 32; i += 8)
        tsm[ty + i][tx] = I[(long long)(r0 + ty + i) * Cc + c0 + tx];
    __syncthreads();
#pragma unroll
    for (int i = 0; i < 32; i += 8) {
        __half h, l;
        fsplit(tsm[tx][ty + i], h, l);
        long long o = obase + (long long)(c0 + ty + i) * R + r0 + tx;
        oh[o] = h; ol[o] = l;
    }
}

// ---------------------------------------------------------------------------
// Causal row softmax, register-resident: one warp per row, row read ONCE
// into registers (len <= 2048 -> <= 64 floats/lane), max/exp/sum in regs,
// halves written once. No fp32 writeback. Same per-lane accumulation order
// as before -> bit-identical output.
// ---------------------------------------------------------------------------
__global__ void softmax_kernel(const float* __restrict__ scores,
                               __half* __restrict__ ph, __half* __restrict__ pl)
{
    const int warp = threadIdx.x >> 5;
    const int lane = threadIdx.x & 31;
    const long long r = (long long)blockIdx.x * (blockDim.x >> 5) + warp;
    const int s = (int)(r & (SEQL - 1));
    const int len = s + 1;
    const float* row = scores + r * SEQL;
    __half* rh = ph + r * SEQL;
    __half* rl = pl + r * SEQL;

    const int niter = (len + 31) >> 5;     // uniform across the warp (one row/warp)

    float v[64];
    float mx = -INFINITY;
#pragma unroll 8
    for (int i = 0; i < niter; i++) {
        const int j = lane + (i << 5);
        v[i] = (j < len) ? row[j] : -INFINITY;
        mx = fmaxf(mx, v[i]);
    }
#pragma unroll
    for (int o = 16; o > 0; o >>= 1) mx = fmaxf(mx, __shfl_xor_sync(0xffffffffu, mx, o));

    float sum = 0.f;
#pragma unroll 8
    for (int i = 0; i < niter; i++) {
        const int j = lane + (i << 5);
        if (j < len) {
            float e = __expf(v[i] - mx);
            v[i] = e;
            sum += e;
        }
    }
#pragma unroll
    for (int o = 16; o > 0; o >>= 1) sum += __shfl_xor_sync(0xffffffffu, sum, o);

    const float inv = 1.0f / sum;
#pragma unroll 8
    for (int i = 0; i < niter; i++) {
        const int j = lane + (i << 5);
        if (j < len) {
            float p = v[i] * inv;
            __half h, l;
            fsplit(p, h, l);
            rh[j] = h; rl[j] = l;
        }
    }
    const int zend = ((s >> 7) + 1) << 7;
    for (int j = len + lane; j < zend; j += 32) {
        rh[j] = __float2half_rn(0.f); rl[j] = __float2half_rn(0.f);
    }
}

// ---------------------------------------------------------------------------
extern "C" void kernel_launch(void* const* d_in, const int* in_sizes, int n_in,
                              void* d_out, int out_size)
{
    const float* x   = (const float*)d_in[0];
    const float* Wd  = (const float*)d_in[1];
    const float* Wuk = (const float*)d_in[2];
    const float* Wuv = (const float*)d_in[3];
    const float* Wq  = (const float*)d_in[4];
    const float* Wo  = (const float*)d_in[5];
    float* out = (float*)d_out;

#define SYM(p, s) cudaGetSymbolAddress((void**)&p, s)
    __half *xh, *xl, *wdh, *wdl, *wqh, *wql, *wuvh, *wuvl, *woh, *wol, *wukTh, *wukTl;
    __half *lath, *latl, *latTh, *latTl, *qh, *ql, *qlath, *qlatl;
    __half *attnh, *attnl, *ctxh, *ctxl, *vh, *vl;
    float *lat, *sc;
    SYM(xh, g_xh); SYM(xl, g_xl); SYM(wdh, g_wdh); SYM(wdl, g_wdl);
    SYM(wqh, g_wqh); SYM(wql, g_wql); SYM(wuvh, g_wuvh); SYM(wuvl, g_wuvl);
    SYM(woh, g_woh); SYM(wol, g_wol); SYM(wukTh, g_wukTh); SYM(wukTl, g_wukTl);
    SYM(lat, g_lat); SYM(lath, g_lath); SYM(latl, g_latl);
    SYM(latTh, g_latTh); SYM(latTl, g_latTl);
    SYM(qh, g_qh); SYM(ql, g_ql); SYM(qlath, g_qlath); SYM(qlatl, g_qlatl);
    SYM(sc, g_scores); SYM(attnh, g_attnh); SYM(attnl, g_attnl);
    SYM(ctxh, g_ctxh); SYM(ctxl, g_ctxl); SYM(vh, g_vh); SYM(vl, g_vl);
#undef SYM

    static int attr_done = 0;
    if (!attr_done) {
        cudaFuncSetAttribute(mma_gemm<0, 0>, cudaFuncAttributeMaxDynamicSharedMemorySize, SMEM_BYTES);
        cudaFuncSetAttribute(mma_gemm<0, 1>, cudaFuncAttributeMaxDynamicSharedMemorySize, SMEM_BYTES);
        cudaFuncSetAttribute(mma_gemm<0, 2>, cudaFuncAttributeMaxDynamicSharedMemorySize, SMEM_BYTES);
        cudaFuncSetAttribute(mma_gemm<1, 1>, cudaFuncAttributeMaxDynamicSharedMemorySize, SMEM_BYTES);
        cudaFuncSetAttribute(mma_gemm<2, 0>, cudaFuncAttributeMaxDynamicSharedMemorySize, SMEM_BYTES);
        cudaFuncSetAttribute(mma_gemm<3, 1>, cudaFuncAttributeMaxDynamicSharedMemorySize, SMEM_BYTES);
        cudaFuncSetAttribute(mma_gemm<4, 1>, cudaFuncAttributeMaxDynamicSharedMemorySize, SMEM_BYTES);
        attr_done = 1;
    }

    const int MROWS = SB * SEQL;  // 4096
    const dim3 blk(NTHR);
    const float inv_sqrt_dh = 0.08838834764831845f;

    // C0: split inputs/weights
    {
        long long n;
        n = (long long)SB * SEQL * DMODEL;
        cvt_kernel<<<(unsigned)((n + 255) / 256), 256>>>(x, xh, xl, n);
        n = (long long)CLAT * DMODEL;
        cvt_kernel<<<(unsigned)((n + 255) / 256), 256>>>(Wd, wdh, wdl, n);
        n = (long long)HDTOT * DMODEL;
        cvt_kernel<<<(unsigned)((n + 255) / 256), 256>>>(Wq, wqh, wql, n);
        n = (long long)HDTOT * CLAT;
        cvt_kernel<<<(unsigned)((n + 255) / 256), 256>>>(Wuv, wuvh, wuvl, n);
        n = (long long)DMODEL * HDTOT;
        cvt_kernel<<<(unsigned)((n + 255) / 256), 256>>>(Wo, woh, wol, n);
    }
    // T2: wukT halves
    transpose_cvt_kernel<<<dim3(CLAT / 32, DHD / 32, NH), dim3(32, 8)>>>(
        Wuk, wukTh, wukTl, DHD, CLAT);

    // G1: latents = x @ Wd^T   (fp32 + halves)
    mma_gemm<0, 2><<<dim3(CLAT / BN, MROWS / BM, 1), blk, SMEM_BYTES>>>(
        xh, xl, wdh, wdl, lat, lath, latl, DMODEL, DMODEL, DMODEL, CLAT, 1.f);

    // T1: latT halves
    transpose_cvt_kernel<<<dim3(CLAT / 32, SEQL / 32, SB), dim3(32, 8)>>>(
        lat, latTh, latTl, SEQL, CLAT);

    // G2: q = x @ Wq^T  (halves out)
    mma_gemm<0, 1><<<dim3(HDTOT / BN, MROWS / BM, 1), blk, SMEM_BYTES>>>(
        xh, xl, wqh, wql, nullptr, qh, ql, DMODEL, DMODEL, DMODEL, HDTOT, 1.f);

    // G3: q_lat[z] = q_h @ wukT[h]^T   (K=128, halves out)
    mma_gemm<1, 1><<<dim3(CLAT / BN, SEQL / BM, SB * NH), blk, SMEM_BYTES>>>(
        qh, ql, wukTh, wukTl, nullptr, qlath, qlatl, DHD, HDTOT, DHD, CLAT, 1.f);

    // G4: scores = q_lat @ latents^T / sqrt(dh)  (causal, fp32 out)
    mma_gemm<2, 0><<<dim3(SEQL / BN, SEQL / BM, SB * NH), blk, SMEM_BYTES>>>(
        qlath, qlatl, lath, latl, sc, nullptr, nullptr, CLAT, CLAT, CLAT, SEQL, inv_sqrt_dh);

    // G5: softmax -> attn halves (register-resident, single read/exp/write)
    softmax_kernel<<<(unsigned)((long long)SB * NH * SEQL / 8), 256>>>(sc, attnh, attnl);

    // G6: ctx = attn @ latT^T  (K_eff per row tile, halves out)
    mma_gemm<3, 1><<<dim3(CLAT / BN, SEQL / BM, SB * NH), blk, SMEM_BYTES>>>(
        attnh, attnl, latTh, latTl, nullptr, ctxh, ctxl, SEQL, SEQL, SEQL, CLAT, 1.f);

    // G7: v_h = ctx @ Wuv_h^T  (halves out)
    mma_gemm<4, 1><<<dim3(DHD / BN, SEQL / BM, SB * NH), blk, SMEM_BYTES>>>(
        ctxh, ctxl, wuvh, wuvl, nullptr, vh, vl, CLAT, CLAT, CLAT, HDTOT, 1.f);

    // G8: out = v @ Wo^T  (fp32 out)
    mma_gemm<0, 0><<<dim3(DMODEL / BN, MROWS / BM, 1), blk, SMEM_BYTES>>>(
        vh, vl, woh, wol, out, nullptr, nullptr, HDTOT, HDTOT, HDTOT, DMODEL, 1.f);
}

// round 17
// speedup vs baseline: 1.2775x; 1.1363x over previous
#include <cuda_runtime.h>
#include <cuda_fp16.h>
#include <math.h>
#include <stdint.h>

// ============================================================================
// MLA prefill — round 17: R16 + 2-pass split mma on the attention GEMMs.
// G4 (scores) and G6 (ctx) are 57% of tensor work; dropping the hi(A)*lo(B)
// pass costs ~2^-12 relative error (predicted final rel_err 1-4e-4, gate
// 1e-3) and means the B-lo tile is never loaded in those kernels:
// -33% mma count and -25% memory traffic on G4/G6.
// ============================================================================

#define SB     2
#define SEQL   2048
#define DMODEL 2048
#define CLAT   512
#define NH     16
#define DHD    128
#define HDTOT  2048

// ---------------- scratch ----------------
__device__ __half g_xh [(size_t)SB * SEQL * DMODEL],  g_xl [(size_t)SB * SEQL * DMODEL];
__device__ __half g_wdh[(size_t)CLAT * DMODEL],       g_wdl[(size_t)CLAT * DMODEL];
__device__ __half g_wqh[(size_t)HDTOT * DMODEL],      g_wql[(size_t)HDTOT * DMODEL];
__device__ __half g_wuvh[(size_t)HDTOT * CLAT],       g_wuvl[(size_t)HDTOT * CLAT];
__device__ __half g_woh[(size_t)DMODEL * HDTOT],      g_wol[(size_t)DMODEL * HDTOT];
__device__ __half g_wukTh[(size_t)NH * CLAT * DHD],   g_wukTl[(size_t)NH * CLAT * DHD];
__device__ float  g_lat  [(size_t)SB * SEQL * CLAT];
__device__ __half g_lath [(size_t)SB * SEQL * CLAT],  g_latl [(size_t)SB * SEQL * CLAT];
__device__ __half g_latTh[(size_t)SB * CLAT * SEQL],  g_latTl[(size_t)SB * CLAT * SEQL];
__device__ __half g_qh   [(size_t)SB * SEQL * HDTOT], g_ql   [(size_t)SB * SEQL * HDTOT];
__device__ __half g_qlath[(size_t)SB * NH * SEQL * CLAT], g_qlatl[(size_t)SB * NH * SEQL * CLAT];
__device__ float  g_scores[(size_t)SB * NH * SEQL * SEQL];
__device__ __half g_attnh[(size_t)SB * NH * SEQL * SEQL], g_attnl[(size_t)SB * NH * SEQL * SEQL];
__device__ __half g_ctxh [(size_t)SB * NH * SEQL * CLAT], g_ctxl [(size_t)SB * NH * SEQL * CLAT];
__device__ __half g_vh   [(size_t)SB * SEQL * HDTOT], g_vl   [(size_t)SB * SEQL * HDTOT];

#define BM 128
#define BN 128
#define BK 32
#define ROWH 40      // smem row pitch in halves: ldmatrix-conflict-free
#define TILEH (BM * ROWH)
#define SMEM_BYTES (2 * 4 * TILEH * 2)          // 81920 B
#define NTHR 128                                 // 4 warps, 2m x 2n

// m16n8k16 fp16 mma, fp32 accumulate.
static __device__ __forceinline__ void mma_16816(float* d, const uint32_t* a,
                                                 const uint32_t* b) {
    asm("mma.sync.aligned.m16n8k16.row.col.f32.f16.f16.f32 "
        "{%0,%1,%2,%3}, {%4,%5,%6,%7}, {%8,%9}, {%0,%1,%2,%3};"
        : "+f"(d[0]), "+f"(d[1]), "+f"(d[2]), "+f"(d[3])
        : "r"(a[0]), "r"(a[1]), "r"(a[2]), "r"(a[3]), "r"(b[0]), "r"(b[1]));
}

static __device__ __forceinline__ void ldsm_x4(uint32_t& r0, uint32_t& r1,
                                               uint32_t& r2, uint32_t& r3,
                                               uint32_t addr) {
    asm volatile("ldmatrix.sync.aligned.m8n8.x4.shared.b16 {%0,%1,%2,%3}, [%4];"
                 : "=r"(r0), "=r"(r1), "=r"(r2), "=r"(r3) : "r"(addr));
}

static __device__ __forceinline__ void fsplit(float f, __half& h, __half& l) {
    h = __float2half_rn(f);
    l = __float2half_rn(f - __half2float(h));
}

// cp.async one 128x32-half tile (8KB): 512 16B chunks, 4 per thread (128 thr).
static __device__ __forceinline__ void pf_tile(__half* s, const __half* g, int ld, int tid) {
#pragma unroll
    for (int i = 0; i < 4; i++) {
        const int idx = tid + i * NTHR;
        const int r = idx >> 2;
        const int c = (idx & 3) << 3;
        unsigned dst = (unsigned)__cvta_generic_to_shared(s + r * ROWH + c);
        asm volatile("cp.async.cg.shared.global [%0], [%1], 16;"
                     :: "r"(dst), "l"(g + (long long)r * ld + c));
    }
}

// ---------------------------------------------------------------------------
// GEMM: C[128m,128n] = alpha * A @ B^T, A[M,K] hi/lo halves, B[N,K] hi/lo.
// MODE 0: plain. 1: G3. 2: G4 (causal skip). 3: G6 (K_eff). 4: G7.
// OUTK 0: fp32 C. 1: hi/lo half C. 2: both.
// NPASS 3: hh+hl+lh. 2: hh+lh (B-lo never loaded).
// 128 threads = 4 warps (2m x 2n); warp tile 64x64 = 4x8 m16n8k16 atoms.
// ---------------------------------------------------------------------------
template<int MODE, int OUTK, int NPASS>
__global__ void __launch_bounds__(NTHR)
mma_gemm(const __half* __restrict__ Ah, const __half* __restrict__ Al,
         const __half* __restrict__ Bh, const __half* __restrict__ Bl,
         float* __restrict__ C, __half* __restrict__ Ch, __half* __restrict__ Cl,
         int K, int lda, int ldb, int ldc, float alpha)
{
    const int bn = blockIdx.x;
    const int bm = blockIdx.y;
    const int z  = blockIdx.z;

    if (MODE == 2 && bn > bm) return;

    long long aoff = 0, boff = 0, coff = 0;
    if (MODE == 1) {
        int b = z >> 4, h = z & 15;
        aoff = (long long)b * SEQL * HDTOT + (long long)h * DHD;
        boff = (long long)h * CLAT * DHD;
        coff = (long long)z * SEQL * CLAT;
    } else if (MODE == 2) {
        aoff = (long long)z * SEQL * CLAT;
        boff = (long long)(z >> 4) * SEQL * CLAT;
        coff = (long long)z * SEQL * SEQL;
    } else if (MODE == 3) {
        aoff = (long long)z * SEQL * SEQL;
        boff = (long long)(z >> 4) * CLAT * SEQL;
        coff = (long long)z * SEQL * CLAT;
    } else if (MODE == 4) {
        int b = z >> 4, h = z & 15;
        aoff = (long long)z * SEQL * CLAT;
        boff = (long long)h * DHD * CLAT;
        coff = (long long)b * SEQL * HDTOT + (long long)h * DHD;
    }

    const int Keff = (MODE == 3) ? min(K, (bm + 1) * BM) : K;
    const int nkt = Keff / BK;

    const __half* Abh = Ah + aoff + (long long)bm * BM * lda;
    const __half* Abl = Al + aoff + (long long)bm * BM * lda;
    const __half* Bbh = Bh + boff + (long long)bn * BN * ldb;
    const __half* Bbl = Bl + boff + (long long)bn * BN * ldb;
    const long long cbase = coff + (long long)bm * BM * ldc + (long long)bn * BN;

    extern __shared__ __half dynsm[];
#define SMT(buf, op) (dynsm + ((buf) * 4 + (op)) * TILEH)

    const int tid  = threadIdx.x;
    const int lane = tid & 31;
    const int w    = tid >> 5;          // 0..3
    const int mo = (w >> 1) * 64;       // 0 / 64
    const int no = (w & 1) * 64;        // 0 / 64
    const int g  = lane >> 2;
    const int t  = lane & 3;

    const int a_row  = mo + (lane & 7) + ((lane >> 3) & 1) * 8;
    const int a_koff = (lane >> 4) * 8;
    const int b_row  = no + (lane & 7) + ((lane >> 4) & 1) * 8;
    const int b_koff = ((lane >> 3) & 1) * 8;

    float acc[4][8][4];
#pragma unroll
    for (int mt = 0; mt < 4; mt++)
#pragma unroll
        for (int nt = 0; nt < 8; nt++)
#pragma unroll
            for (int e = 0; e < 4; e++) acc[mt][nt][e] = 0.f;

    pf_tile(SMT(0, 0), Abh, lda, tid);
    pf_tile(SMT(0, 1), Abl, lda, tid);
    pf_tile(SMT(0, 2), Bbh, ldb, tid);
    if (NPASS == 3) pf_tile(SMT(0, 3), Bbl, ldb, tid);
    asm volatile("cp.async.commit_group;");

    for (int kt = 0; kt < nkt; ++kt) {
        const int buf = kt & 1;
        if (kt + 1 < nkt) {
            const long long ko = (long long)(kt + 1) * BK;
            pf_tile(SMT(buf ^ 1, 0), Abh + ko, lda, tid);
            pf_tile(SMT(buf ^ 1, 1), Abl + ko, lda, tid);
            pf_tile(SMT(buf ^ 1, 2), Bbh + ko, ldb, tid);
            if (NPASS == 3) pf_tile(SMT(buf ^ 1, 3), Bbl + ko, ldb, tid);
            asm volatile("cp.async.commit_group;");
            asm volatile("cp.async.wait_group 1;");
        } else {
            asm volatile("cp.async.wait_group 0;");
        }
        __syncthreads();

        const uint32_t s_ah = (uint32_t)__cvta_generic_to_shared(SMT(buf, 0));
        const uint32_t s_al = (uint32_t)__cvta_generic_to_shared(SMT(buf, 1));
        const uint32_t s_bh = (uint32_t)__cvta_generic_to_shared(SMT(buf, 2));
        const uint32_t s_bl = (uint32_t)__cvta_generic_to_shared(SMT(buf, 3));

#pragma unroll
        for (int ks = 0; ks < 2; ks++) {        // two k16 steps per BK=32 tile
            const int kk = ks * 16;
            uint32_t ah[4][4], al[4][4], bh[8][2], bl[8][2];
#pragma unroll
            for (int mt = 0; mt < 4; mt++) {
                const uint32_t off = 2u * ((a_row + mt * 16) * ROWH + kk + a_koff);
                ldsm_x4(ah[mt][0], ah[mt][1], ah[mt][2], ah[mt][3], s_ah + off);
                ldsm_x4(al[mt][0], al[mt][1], al[mt][2], al[mt][3], s_al + off);
            }
#pragma unroll
            for (int p = 0; p < 4; p++) {       // nt pairs (2p, 2p+1)
                const uint32_t off = 2u * ((b_row + p * 16) * ROWH + kk + b_koff);
                ldsm_x4(bh[2 * p][0], bh[2 * p][1], bh[2 * p + 1][0], bh[2 * p + 1][1],
                        s_bh + off);
                if (NPASS == 3)
                    ldsm_x4(bl[2 * p][0], bl[2 * p][1], bl[2 * p + 1][0], bl[2 * p + 1][1],
                            s_bl + off);
            }

            // pass-outer ordering; per-acc addition order: hh, (hl,) lh.
#pragma unroll
            for (int mt = 0; mt < 4; mt++)
#pragma unroll
                for (int nt = 0; nt < 8; nt++)
                    mma_16816(acc[mt][nt], ah[mt], bh[nt]);
            if (NPASS == 3) {
#pragma unroll
                for (int mt = 0; mt < 4; mt++)
#pragma unroll
                    for (int nt = 0; nt < 8; nt++)
                        mma_16816(acc[mt][nt], ah[mt], bl[nt]);
            }
#pragma unroll
            for (int mt = 0; mt < 4; mt++)
#pragma unroll
                for (int nt = 0; nt < 8; nt++)
                    mma_16816(acc[mt][nt], al[mt], bh[nt]);
        }
        __syncthreads();
    }
#undef SMT

#pragma unroll
    for (int mt = 0; mt < 4; mt++) {
        const int r0 = mo + mt * 16 + g;
#pragma unroll
        for (int nt = 0; nt < 8; nt++) {
            const int ccol = no + nt * 8 + 2 * t;
            const long long i0 = cbase + (long long)r0 * ldc + ccol;
            const long long i1 = cbase + (long long)(r0 + 8) * ldc + ccol;
            float f0 = acc[mt][nt][0] * alpha, f1 = acc[mt][nt][1] * alpha;
            float f2 = acc[mt][nt][2] * alpha, f3 = acc[mt][nt][3] * alpha;
            if (OUTK == 0 || OUTK == 2) {
                *reinterpret_cast<float2*>(C + i0) = make_float2(f0, f1);
                *reinterpret_cast<float2*>(C + i1) = make_float2(f2, f3);
            }
            if (OUTK == 1 || OUTK == 2) {
                __half h0, l0, h1, l1, h2, l2, h3, l3;
                fsplit(f0, h0, l0); fsplit(f1, h1, l1);
                fsplit(f2, h2, l2); fsplit(f3, h3, l3);
                *reinterpret_cast<__half2*>(Ch + i0) = __halves2half2(h0, h1);
                *reinterpret_cast<__half2*>(Cl + i0) = __halves2half2(l0, l1);
                *reinterpret_cast<__half2*>(Ch + i1) = __halves2half2(h2, h3);
                *reinterpret_cast<__half2*>(Cl + i1) = __halves2half2(l2, l3);
            }
        }
    }
}

// ---------------------------------------------------------------------------
__global__ void cvt_kernel(const float* __restrict__ in, __half* __restrict__ oh,
                           __half* __restrict__ ol, long long n)
{
    long long i = (long long)blockIdx.x * blockDim.x + threadIdx.x;
    if (i < n) {
        __half h, l;
        fsplit(in[i], h, l);
        oh[i] = h; ol[i] = l;
    }
}

// ---------------------------------------------------------------------------
__global__ void transpose_cvt_kernel(const float* __restrict__ in,
                                     __half* __restrict__ oh, __half* __restrict__ ol,
                                     int R, int Cc)
{
    __shared__ float tsm[32][33];
    const int z = blockIdx.z;
    const int r0 = blockIdx.y * 32, c0 = blockIdx.x * 32;
    const float* I = in + (long long)z * R * Cc;
    const long long obase = (long long)z * R * Cc;
    const int tx = threadIdx.x, ty = threadIdx.y;
#pragma unroll
    for (int i = 0; i < 32; i += 8)
        tsm[ty + i][tx] = I[(long long)(r0 + ty + i) * Cc + c0 + tx];
    __syncthreads();
#pragma unroll
    for (int i = 0; i < 32; i += 8) {
        __half h, l;
        fsplit(tsm[tx][ty + i], h, l);
        long long o = obase + (long long)(c0 + ty + i) * R + r0 + tx;
        oh[o] = h; ol[o] = l;
    }
}

// ---------------------------------------------------------------------------
// Causal row softmax, register-resident (R16).
// ---------------------------------------------------------------------------
__global__ void softmax_kernel(const float* __restrict__ scores,
                               __half* __restrict__ ph, __half* __restrict__ pl)
{
    const int warp = threadIdx.x >> 5;
    const int lane = threadIdx.x & 31;
    const long long r = (long long)blockIdx.x * (blockDim.x >> 5) + warp;
    const int s = (int)(r & (SEQL - 1));
    const int len = s + 1;
    const float* row = scores + r * SEQL;
    __half* rh = ph + r * SEQL;
    __half* rl = pl + r * SEQL;

    const int niter = (len + 31) >> 5;

    float v[64];
    float mx = -INFINITY;
#pragma unroll 8
    for (int i = 0; i < niter; i++) {
        const int j = lane + (i << 5);
        v[i] = (j < len) ? row[j] : -INFINITY;
        mx = fmaxf(mx, v[i]);
    }
#pragma unroll
    for (int o = 16; o > 0; o >>= 1) mx = fmaxf(mx, __shfl_xor_sync(0xffffffffu, mx, o));

    float sum = 0.f;
#pragma unroll 8
    for (int i = 0; i < niter; i++) {
        const int j = lane + (i << 5);
        if (j < len) {
            float e = __expf(v[i] - mx);
            v[i] = e;
            sum += e;
        }
    }
#pragma unroll
    for (int o = 16; o > 0; o >>= 1) sum += __shfl_xor_sync(0xffffffffu, sum, o);

    const float inv = 1.0f / sum;
#pragma unroll 8
    for (int i = 0; i < niter; i++) {
        const int j = lane + (i << 5);
        if (j < len) {
            float p = v[i] * inv;
            __half h, l;
            fsplit(p, h, l);
            rh[j] = h; rl[j] = l;
        }
    }
    const int zend = ((s >> 7) + 1) << 7;
    for (int j = len + lane; j < zend; j += 32) {
        rh[j] = __float2half_rn(0.f); rl[j] = __float2half_rn(0.f);
    }
}

// ---------------------------------------------------------------------------
extern "C" void kernel_launch(void* const* d_in, const int* in_sizes, int n_in,
                              void* d_out, int out_size)
{
    const float* x   = (const float*)d_in[0];
    const float* Wd  = (const float*)d_in[1];
    const float* Wuk = (const float*)d_in[2];
    const float* Wuv = (const float*)d_in[3];
    const float* Wq  = (const float*)d_in[4];
    const float* Wo  = (const float*)d_in[5];
    float* out = (float*)d_out;

#define SYM(p, s) cudaGetSymbolAddress((void**)&p, s)
    __half *xh, *xl, *wdh, *wdl, *wqh, *wql, *wuvh, *wuvl, *woh, *wol, *wukTh, *wukTl;
    __half *lath, *latl, *latTh, *latTl, *qh, *ql, *qlath, *qlatl;
    __half *attnh, *attnl, *ctxh, *ctxl, *vh, *vl;
    float *lat, *sc;
    SYM(xh, g_xh); SYM(xl, g_xl); SYM(wdh, g_wdh); SYM(wdl, g_wdl);
    SYM(wqh, g_wqh); SYM(wql, g_wql); SYM(wuvh, g_wuvh); SYM(wuvl, g_wuvl);
    SYM(woh, g_woh); SYM(wol, g_wol); SYM(wukTh, g_wukTh); SYM(wukTl, g_wukTl);
    SYM(lat, g_lat); SYM(lath, g_lath); SYM(latl, g_latl);
    SYM(latTh, g_latTh); SYM(latTl, g_latTl);
    SYM(qh, g_qh); SYM(ql, g_ql); SYM(qlath, g_qlath); SYM(qlatl, g_qlatl);
    SYM(sc, g_scores); SYM(attnh, g_attnh); SYM(attnl, g_attnl);
    SYM(ctxh, g_ctxh); SYM(ctxl, g_ctxl); SYM(vh, g_vh); SYM(vl, g_vl);
#undef SYM

    static int attr_done = 0;
    if (!attr_done) {
        cudaFuncSetAttribute(mma_gemm<0, 0, 3>, cudaFuncAttributeMaxDynamicSharedMemorySize, SMEM_BYTES);
        cudaFuncSetAttribute(mma_gemm<0, 1, 3>, cudaFuncAttributeMaxDynamicSharedMemorySize, SMEM_BYTES);
        cudaFuncSetAttribute(mma_gemm<0, 2, 3>, cudaFuncAttributeMaxDynamicSharedMemorySize, SMEM_BYTES);
        cudaFuncSetAttribute(mma_gemm<1, 1, 3>, cudaFuncAttributeMaxDynamicSharedMemorySize, SMEM_BYTES);
        cudaFuncSetAttribute(mma_gemm<2, 0, 2>, cudaFuncAttributeMaxDynamicSharedMemorySize, SMEM_BYTES);
        cudaFuncSetAttribute(mma_gemm<3, 1, 2>, cudaFuncAttributeMaxDynamicSharedMemorySize, SMEM_BYTES);
        cudaFuncSetAttribute(mma_gemm<4, 1, 3>, cudaFuncAttributeMaxDynamicSharedMemorySize, SMEM_BYTES);
        attr_done = 1;
    }

    const int MROWS = SB * SEQL;  // 4096
    const dim3 blk(NTHR);
    const float inv_sqrt_dh = 0.08838834764831845f;

    // C0: split inputs/weights
    {
        long long n;
        n = (long long)SB * SEQL * DMODEL;
        cvt_kernel<<<(unsigned)((n + 255) / 256), 256>>>(x, xh, xl, n);
        n = (long long)CLAT * DMODEL;
        cvt_kernel<<<(unsigned)((n + 255) / 256), 256>>>(Wd, wdh, wdl, n);
        n = (long long)HDTOT * DMODEL;
        cvt_kernel<<<(unsigned)((n + 255) / 256), 256>>>(Wq, wqh, wql, n);
        n = (long long)HDTOT * CLAT;
        cvt_kernel<<<(unsigned)((n + 255) / 256), 256>>>(Wuv, wuvh, wuvl, n);
        n = (long long)DMODEL * HDTOT;
        cvt_kernel<<<(unsigned)((n + 255) / 256), 256>>>(Wo, woh, wol, n);
    }
    // T2: wukT halves
    transpose_cvt_kernel<<<dim3(CLAT / 32, DHD / 32, NH), dim3(32, 8)>>>(
        Wuk, wukTh, wukTl, DHD, CLAT);

    // G1: latents = x @ Wd^T   (fp32 + halves)
    mma_gemm<0, 2, 3><<<dim3(CLAT / BN, MROWS / BM, 1), blk, SMEM_BYTES>>>(
        xh, xl, wdh, wdl, lat, lath, latl, DMODEL, DMODEL, DMODEL, CLAT, 1.f);

    // T1: latT halves
    transpose_cvt_kernel<<<dim3(CLAT / 32, SEQL / 32, SB), dim3(32, 8)>>>(
        lat, latTh, latTl, SEQL, CLAT);

    // G2: q = x @ Wq^T  (halves out)
    mma_gemm<0, 1, 3><<<dim3(HDTOT / BN, MROWS / BM, 1), blk, SMEM_BYTES>>>(
        xh, xl, wqh, wql, nullptr, qh, ql, DMODEL, DMODEL, DMODEL, HDTOT, 1.f);

    // G3: q_lat[z] = q_h @ wukT[h]^T   (K=128, halves out)
    mma_gemm<1, 1, 3><<<dim3(CLAT / BN, SEQL / BM, SB * NH), blk, SMEM_BYTES>>>(
        qh, ql, wukTh, wukTl, nullptr, qlath, qlatl, DHD, HDTOT, DHD, CLAT, 1.f);

    // G4: scores = q_lat @ latents^T / sqrt(dh)  (causal, fp32 out, 2-pass)
    mma_gemm<2, 0, 2><<<dim3(SEQL / BN, SEQL / BM, SB * NH), blk, SMEM_BYTES>>>(
        qlath, qlatl, lath, latl, sc, nullptr, nullptr, CLAT, CLAT, CLAT, SEQL, inv_sqrt_dh);

    // G5: softmax -> attn halves (register-resident)
    softmax_kernel<<<(unsigned)((long long)SB * NH * SEQL / 8), 256>>>(sc, attnh, attnl);

    // G6: ctx = attn @ latT^T  (K_eff per row tile, halves out, 2-pass)
    mma_gemm<3, 1, 2><<<dim3(CLAT / BN, SEQL / BM, SB * NH), blk, SMEM_BYTES>>>(
        attnh, attnl, latTh, latTl, nullptr, ctxh, ctxl, SEQL, SEQL, SEQL, CLAT, 1.f);

    // G7: v_h = ctx @ Wuv_h^T  (halves out)
    mma_gemm<4, 1, 3><<<dim3(DHD / BN, SEQL / BM, SB * NH), blk, SMEM_BYTES>>>(
        ctxh, ctxl, wuvh, wuvl, nullptr, vh, vl, CLAT, CLAT, CLAT, HDTOT, 1.f);

    // G8: out = v @ Wo^T  (fp32 out)
    mma_gemm<0, 0, 3><<<dim3(DMODEL / BN, MROWS / BM, 1), blk, SMEM_BYTES>>>(
        vh, vl, woh, wol, out, nullptr, nullptr, HDTOT, HDTOT, HDTOT, DMODEL, 1.f);
}